// round 11
// baseline (speedup 1.0000x reference)
#include <cuda_runtime.h>
#include <cuda_bf16.h>
#include <cuda_fp16.h>
#include <cstdint>
#include <math.h>

#define BATCH 2
#define LSEQ 2048
#define DMODEL 1024
#define NHEAD 16
#define DHEAD 64
#define UTOP 40
#define MROWS (BATCH*LSEQ)          // 4096
#define BHL (BATCH*NHEAD*LSEQ)      // 65536
#define KSPLIT 8
#define KS_KEYS (LSEQ/KSPLIT)       // 256
#define MODROWS 640
#define DD (DMODEL*DMODEL)

// ---------------- scratch ----------------
__device__ float g_Q[BATCH*NHEAD*LSEQ*DHEAD];
__device__ float g_K[BATCH*NHEAD*LSEQ*DHEAD];
__device__ float g_V[BATCH*NHEAD*LSEQ*DHEAD];
__device__ float g_M[BHL];
__device__ int   g_top[BATCH*NHEAD*UTOP];
__device__ float g_ctx[BATCH*NHEAD*UTOP*DHEAD];
__device__ float g_vpart[BATCH*NHEAD*KSPLIT*DHEAD];
__device__ float g_vmean[BATCH*NHEAD*DHEAD];
__device__ __nv_bfloat16 g_xbh[MROWS*DMODEL], g_xbl[MROWS*DMODEL];
__device__ __half        g_xfh[MROWS*DMODEL], g_xfl[MROWS*DMODEL];
__device__ __nv_bfloat16 g_wbh[2*DD], g_wbl[2*DD];   // [Wq ; Wkv_K] bf16 hi/lo
__device__ __half        g_wv[DD];                   // Wkv_V fp16
__device__ __half        g_wo[DD];                   // Wout fp16
__device__ __half        g_cmh[BATCH*MODROWS*DMODEL], g_cml[BATCH*MODROWS*DMODEL];
__device__ float g_pm[BATCH*NHEAD*UTOP*KSPLIT];
__device__ float g_ps[BATCH*NHEAD*UTOP*KSPLIT];
__device__ float g_pa[BATCH*NHEAD*UTOP*KSPLIT*DHEAD];
__device__ unsigned char g_selu[BATCH*NHEAD*LSEQ];
__device__ int   g_flags[BATCH*LSEQ];
__device__ int   g_rowlist[BATCH*MODROWS];
__device__ float g_baseout[BATCH*DMODEL];

// ================= helpers =================
#define CP_ASYNC16(dst, src) \
    asm volatile("cp.async.cg.shared.global [%0], [%1], 16;" :: "r"(dst), "l"(src))
#define CP_COMMIT() asm volatile("cp.async.commit_group;" ::: "memory")

__device__ __forceinline__ uint32_t smem_u32(const void* p) {
    uint32_t a;
    asm("{ .reg .u64 t; cvta.to.shared.u64 t, %1; cvt.u32.u64 %0, t; }" : "=r"(a) : "l"(p));
    return a;
}
__device__ __forceinline__ void mma_bf(float* c, const uint32_t* a, const uint32_t* b) {
    asm volatile("mma.sync.aligned.m16n8k16.row.col.f32.bf16.bf16.f32 "
        "{%0,%1,%2,%3}, {%4,%5,%6,%7}, {%8,%9}, {%0,%1,%2,%3};"
        : "+f"(c[0]), "+f"(c[1]), "+f"(c[2]), "+f"(c[3])
        : "r"(a[0]), "r"(a[1]), "r"(a[2]), "r"(a[3]), "r"(b[0]), "r"(b[1]));
}
__device__ __forceinline__ void mma_f16(float* c, const uint32_t* a, const uint32_t* b) {
    asm volatile("mma.sync.aligned.m16n8k16.row.col.f32.f16.f16.f32 "
        "{%0,%1,%2,%3}, {%4,%5,%6,%7}, {%8,%9}, {%0,%1,%2,%3};"
        : "+f"(c[0]), "+f"(c[1]), "+f"(c[2]), "+f"(c[3])
        : "r"(a[0]), "r"(a[1]), "r"(a[2]), "r"(a[3]), "r"(b[0]), "r"(b[1]));
}
__device__ __forceinline__ void ldsm_x4(uint32_t* r, uint32_t addr) {
    asm volatile("ldmatrix.sync.aligned.m8n8.x4.shared.b16 {%0,%1,%2,%3}, [%4];"
        : "=r"(r[0]), "=r"(r[1]), "=r"(r[2]), "=r"(r[3]) : "r"(addr));
}
// 64B rows, 4x16B blocks, XOR swizzle by row&3
__device__ __forceinline__ uint32_t sw_addr(uint32_t tile, int row, int cb) {
    return tile + (uint32_t)row * 64 + (uint32_t)((cb ^ (row & 3)) << 4);
}

// ================= conversions =================
__global__ void splitX(const float* __restrict__ src)
{
    int i = blockIdx.x * blockDim.x + threadIdx.x;
    float v = src[i];
    __nv_bfloat16 bh = __float2bfloat16(v);
    g_xbh[i] = bh;
    g_xbl[i] = __float2bfloat16(v - __bfloat162float(bh));
    __half fh = __float2half(v);
    g_xfh[i] = fh;
    g_xfl[i] = __float2half(v - __half2float(fh));
}
__global__ void splitWb(const float* __restrict__ Wq, const float* __restrict__ Wkv)
{
    int i = blockIdx.x * blockDim.x + threadIdx.x;
    float v = (i < DD) ? Wq[i] : Wkv[i - DD];
    __nv_bfloat16 h = __float2bfloat16(v);
    g_wbh[i] = h;
    g_wbl[i] = __float2bfloat16(v - __bfloat162float(h));
}
__global__ void convH(const float* __restrict__ Wkv, const float* __restrict__ Wout)
{
    int i = blockIdx.x * blockDim.x + threadIdx.x;
    if (i < DD) g_wv[i] = __float2half(Wkv[DD + i]);
    else        g_wo[i - DD] = __float2half(Wout[i - DD]);
}

// ================= tensor-core GEMM (256x128 tile, 64x64 warp tiles) =========
// 8 warps 4x2, K-chunk 32, 3-stage cp.async pipeline, XOR-swizzled 64B rows,
// one __syncthreads per chunk, 1 CTA/SM. mma:LDSM ratio 6 (vs 4 before).
// KIND 0: merged QKV. blockIdx.x 0..15 -> QK cols (bf16 3-pass),
//                     blockIdx.x 16..23 -> V cols (fp16 2-pass).
// KIND 1: OUT (Cmod fp16 2-pass, rowlist scatter).
#define ATILE 16384                  // 256 rows x 64B
#define BTILE 8192                   // 128 rows x 64B
#define STAGE_SZ (2*ATILE + 2*BTILE) // 49152
#define GSMEM (3*STAGE_SZ)           // 147456
#define NCHUNK 32
#define NSTAGE 3

template<int KIND>
__global__ void __launch_bounds__(256, 1) gemm_tc(
    const float* __restrict__ bias0, const float* __restrict__ bias1, float* __restrict__ out)
{
    extern __shared__ char smem[];
    uint32_t sb = smem_u32(smem);
    const int t = threadIdx.x;
    const int wid = t >> 5;
    const int lane = t & 31;
    const int g  = lane >> 2;
    const int tg = lane & 3;
    const int wm = wid >> 1;      // 0..3 (64-row blocks)
    const int wn = wid & 1;       // 0..1 (64-col blocks)
    const int m0 = blockIdx.y * 256;

    bool qk;
    int n0;
    const char *A0, *A1, *B0, *B1;
    if (KIND == 0) {
        qk = (blockIdx.x < 16);
        n0 = qk ? blockIdx.x * 128 : (blockIdx.x - 16) * 128;
        A0 = qk ? (const char*)g_xbh : (const char*)g_xfh;
        A1 = qk ? (const char*)g_xbl : (const char*)g_xfl;
        B0 = qk ? (const char*)g_wbh : (const char*)g_wv;
        B1 = (const char*)g_wbl;      // only read when qk
    } else {
        qk = false;
        n0 = blockIdx.x * 128;
        A0 = (const char*)g_cmh; A1 = (const char*)g_cml;
        B0 = (const char*)g_wo;  B1 = nullptr;
    }

    const int arow = lane & 15;
    const int acb  = (lane >> 4) & 1;
    const int brow = (lane & 7) + ((lane >> 4) & 1) * 8;
    const int bcb  = (lane >> 3) & 1;

    float c[4][8][4];
    #pragma unroll
    for (int i = 0; i < 4; i++)
        #pragma unroll
        for (int j = 0; j < 8; j++)
            #pragma unroll
            for (int q = 0; q < 4; q++) c[i][j][q] = 0.f;

    auto load_chunk = [&](uint32_t stage, int kc) {
        int kb = kc * 64;
        // A: 256 rows x 4 cb = 1024 cp ops
        #pragma unroll
        for (int r = 0; r < 4; r++) {
            int j   = t + r * 256;
            int row = j >> 2;
            int cb  = j & 3;
            uint32_t d = (uint32_t)row * 64 + (uint32_t)((cb ^ (row & 3)) << 4);
            int off = kb + cb * 16;
            CP_ASYNC16(stage + 0*ATILE + d, A0 + (size_t)(m0 + row) * 2048 + off);
            CP_ASYNC16(stage + 1*ATILE + d, A1 + (size_t)(m0 + row) * 2048 + off);
        }
        // B: 128 rows x 4 cb = 512 cp ops
        #pragma unroll
        for (int r = 0; r < 2; r++) {
            int j   = t + r * 256;
            int row = j >> 2;
            int cb  = j & 3;
            uint32_t d = (uint32_t)row * 64 + (uint32_t)((cb ^ (row & 3)) << 4);
            int off = kb + cb * 16;
            CP_ASYNC16(stage + 2*ATILE + d, B0 + (size_t)(n0 + row) * 2048 + off);
            if (KIND == 0 && qk)
                CP_ASYNC16(stage + 2*ATILE + BTILE + d, B1 + (size_t)(n0 + row) * 2048 + off);
        }
    };

    load_chunk(sb, 0);                CP_COMMIT();
    load_chunk(sb + STAGE_SZ, 1);     CP_COMMIT();

    int stg = 0;
    for (int kc = 0; kc < NCHUNK; kc++) {
        if (kc < NCHUNK - 1) asm volatile("cp.async.wait_group 1;" ::: "memory");
        else                 asm volatile("cp.async.wait_group 0;" ::: "memory");
        __syncthreads();

        uint32_t Ah = sb + stg * STAGE_SZ + 0*ATILE;
        uint32_t Al = sb + stg * STAGE_SZ + 1*ATILE;
        uint32_t Bh = sb + stg * STAGE_SZ + 2*ATILE;
        uint32_t Bl = Bh + BTILE;

        #pragma unroll
        for (int ks = 0; ks < 2; ks++) {
            uint32_t ah[4][4], al[4][4];
            #pragma unroll
            for (int i = 0; i < 4; i++) {
                int row = wm * 64 + i * 16 + arow;
                int cb  = ks * 2 + acb;
                ldsm_x4(ah[i], sw_addr(Ah, row, cb));
                ldsm_x4(al[i], sw_addr(Al, row, cb));
            }
            #pragma unroll
            for (int jj = 0; jj < 4; jj++) {
                int row = wn * 64 + jj * 16 + brow;
                int cb  = ks * 2 + bcb;
                if (KIND == 0 && qk) {
                    uint32_t bh[4], bl[4];
                    ldsm_x4(bh, sw_addr(Bh, row, cb));
                    ldsm_x4(bl, sw_addr(Bl, row, cb));
                    #pragma unroll
                    for (int i = 0; i < 4; i++) {
                        mma_bf(c[i][2*jj],   ah[i], bh);
                        mma_bf(c[i][2*jj],   ah[i], bl);
                        mma_bf(c[i][2*jj],   al[i], bh);
                        mma_bf(c[i][2*jj+1], ah[i], bh + 2);
                        mma_bf(c[i][2*jj+1], ah[i], bl + 2);
                        mma_bf(c[i][2*jj+1], al[i], bh + 2);
                    }
                } else {
                    uint32_t bq[4];
                    ldsm_x4(bq, sw_addr(Bh, row, cb));
                    #pragma unroll
                    for (int i = 0; i < 4; i++) {
                        mma_f16(c[i][2*jj],   ah[i], bq);
                        mma_f16(c[i][2*jj],   al[i], bq);
                        mma_f16(c[i][2*jj+1], ah[i], bq + 2);
                        mma_f16(c[i][2*jj+1], al[i], bq + 2);
                    }
                }
            }
        }
        if (kc + 2 < NCHUNK) {
            int nstg = stg + 2; if (nstg >= NSTAGE) nstg -= NSTAGE;
            load_chunk(sb + nstg * STAGE_SZ, kc + 2);
            CP_COMMIT();
        }
        stg = (stg + 1 == NSTAGE) ? 0 : stg + 1;
    }

    // epilogue
    #pragma unroll
    for (int i = 0; i < 4; i++) {
        #pragma unroll
        for (int j = 0; j < 8; j++) {
            #pragma unroll
            for (int half = 0; half < 2; half++) {
                int m = m0 + wm * 64 + i * 16 + g + half * 8;
                int nl = wn * 64 + j * 8 + 2 * tg;       // 0..127 within tile
                float v0 = c[i][j][half*2 + 0];
                float v1 = c[i][j][half*2 + 1];
                if (KIND == 0) {
                    int ncol = blockIdx.x * 128 + nl;     // 0..3071
                    int b_ = m >> 11, l = m & (LSEQ - 1);
                    int which = ncol >> 10;               // 0=Q 1=K 2=V
                    int nloc  = ncol & 1023;
                    int h = nloc >> 6, dh = nloc & 63;
                    const float* bias = (ncol < DMODEL) ? (bias0 + ncol) : (bias1 + ncol - DMODEL);
                    float* dst = (which == 0 ? g_Q : which == 1 ? g_K : g_V)
                               + (((size_t)(b_ * NHEAD + h)) * LSEQ + l) * DHEAD + dh;
                    *(float2*)dst = make_float2(v0 + bias[0], v1 + bias[1]);
                } else {
                    int n = n0 + nl;
                    int b_ = m / MODROWS;
                    int i_ = m - b_ * MODROWS;
                    int l  = g_rowlist[b_ * MODROWS + i_];
                    *(float2*)(out + ((size_t)(b_ * LSEQ + l)) * DMODEL + n) =
                        make_float2(v0 + bias0[n], v1 + bias0[n + 1]);
                }
            }
        }
    }
}

// ================= M scores (fp32, 2 queries per warp) =================
__global__ void score_m_kernel(const int* __restrict__ idxs)
{
    int warp = (blockIdx.x * blockDim.x + threadIdx.x) >> 5;
    int lane = threadIdx.x & 31;
    int bh = warp / (LSEQ/2);
    int l0 = (warp % (LSEQ/2)) * 2;
    const float* qr = g_Q + ((size_t)bh*LSEQ + l0) * DHEAD;
    float qa0 = qr[lane],         qa1 = qr[lane + 32];
    float qb0 = qr[DHEAD + lane], qb1 = qr[DHEAD + lane + 32];
    float mxa = -1e30f, sma = 0.f;
    float mxb = -1e30f, smb = 0.f;
    const float* Kb = g_K + (size_t)bh*LSEQ*DHEAD;
    #pragma unroll 4
    for (int u = 0; u < UTOP; u++) {
        int kia = idxs[l0*UTOP + u];
        int kib = idxs[(l0+1)*UTOP + u];
        const float* kra = Kb + (size_t)kia*DHEAD;
        const float* krb = Kb + (size_t)kib*DHEAD;
        float sa = qa0*kra[lane] + qa1*kra[lane + 32];
        float sb = qb0*krb[lane] + qb1*krb[lane + 32];
        #pragma unroll
        for (int o = 16; o; o >>= 1) {
            sa += __shfl_xor_sync(0xffffffffu, sa, o);
            sb += __shfl_xor_sync(0xffffffffu, sb, o);
        }
        mxa = fmaxf(mxa, sa); sma += sa;
        mxb = fmaxf(mxb, sb); smb += sb;
    }
    if (lane == 0) {
        g_M[(size_t)bh*LSEQ + l0]     = mxa - sma * (1.0f / UTOP);
        g_M[(size_t)bh*LSEQ + l0 + 1] = mxb - smb * (1.0f / UTOP);
    }
}

// ================= top-U =================
__global__ void topk_kernel()
{
    int bh = blockIdx.x;
    __shared__ float vals[LSEQ];
    __shared__ float wv[8];
    __shared__ int   wi[8];
    int t = threadIdx.x, lane = t & 31, wid = t >> 5;
    for (int i = t; i < LSEQ; i += 256) vals[i] = g_M[(size_t)bh*LSEQ + i];
    __syncthreads();
    for (int it = 0; it < UTOP; it++) {
        float v = -2e30f; int bi = 0;
        int base = t * 8;
        #pragma unroll
        for (int j = 0; j < 8; j++) {
            float x = vals[base + j];
            if (x > v) { v = x; bi = base + j; }
        }
        #pragma unroll
        for (int o = 16; o; o >>= 1) {
            float ov = __shfl_xor_sync(0xffffffffu, v, o);
            int   oi = __shfl_xor_sync(0xffffffffu, bi, o);
            if (ov > v) { v = ov; bi = oi; }
        }
        if (lane == 0) { wv[wid] = v; wi[wid] = bi; }
        __syncthreads();
        if (t < 32) {
            float v2 = (t < 8) ? wv[t] : -2e30f;
            int   i2 = (t < 8) ? wi[t] : 0;
            #pragma unroll
            for (int o = 4; o; o >>= 1) {
                float ov = __shfl_xor_sync(0xffffffffu, v2, o);
                int   oi = __shfl_xor_sync(0xffffffffu, i2, o);
                if (ov > v2) { v2 = ov; i2 = oi; }
            }
            if (t == 0) { g_top[bh*UTOP + it] = i2; vals[i2] = -1e30f; }
        }
        __syncthreads();
    }
}

// ================= V mean finish =================
__global__ void vmean_fin()
{
    int bh = blockIdx.x, dh = threadIdx.x;
    float s = 0.f;
    #pragma unroll
    for (int p = 0; p < KSPLIT; p++) s += g_vpart[((size_t)bh*KSPLIT + p)*DHEAD + dh];
    g_vmean[bh*DHEAD + dh] = s * (1.0f / LSEQ);
}

// ================= flash-split attention (+ V-mean partials) =================
__global__ void attn_flash()
{
    extern __shared__ float sm[];
    float* Qt   = sm;
    float* P    = sm + UTOP*DHEAD;
    float* mrow = P + UTOP*KS_KEYS;
    float* srow = mrow + UTOP;
    int ks = blockIdx.x, bh = blockIdx.y;
    int t = threadIdx.x, lane = t & 31, wid = t >> 5;

    for (int i = t; i < UTOP*DHEAD; i += 256) {
        int u = i >> 6, d = i & 63;
        Qt[i] = g_Q[((size_t)bh*LSEQ + g_top[bh*UTOP + u])*DHEAD + d];
    }
    __syncthreads();

    int k = ks * KS_KEYS + t;
    const float4* Kr = (const float4*)(g_K + ((size_t)bh*LSEQ + k)*DHEAD);
    float S[UTOP];
    #pragma unroll
    for (int u = 0; u < UTOP; u++) S[u] = 0.f;
    #pragma unroll
    for (int c = 0; c < 16; c++) {
        float4 kv = Kr[c];
        #pragma unroll
        for (int u = 0; u < UTOP; u++) {
            float4 qv = *(const float4*)(Qt + u*DHEAD + c*4);
            S[u] += kv.x*qv.x + kv.y*qv.y + kv.z*qv.z + kv.w*qv.w;
        }
    }
    #pragma unroll
    for (int u = 0; u < UTOP; u++) P[u*KS_KEYS + t] = S[u] * 0.125f;
    __syncthreads();

    for (int i = 0; i < 5; i++) {
        int u = wid + i*8;
        float* row = P + u*KS_KEYS;
        float m = -1e30f;
        #pragma unroll
        for (int j = 0; j < 8; j++) m = fmaxf(m, row[lane + 32*j]);
        #pragma unroll
        for (int o = 16; o; o >>= 1) m = fmaxf(m, __shfl_xor_sync(0xffffffffu, m, o));
        float s = 0.f;
        #pragma unroll
        for (int j = 0; j < 8; j++) {
            float e = __expf(row[lane + 32*j] - m);
            row[lane + 32*j] = e;
            s += e;
        }
        #pragma unroll
        for (int o = 16; o; o >>= 1) s += __shfl_xor_sync(0xffffffffu, s, o);
        if (lane == 0) { mrow[u] = m; srow[u] = s; }
    }
    __syncthreads();

    int d = t & 63, ug = t >> 6;
    float acc[10];
    #pragma unroll
    for (int i = 0; i < 10; i++) acc[i] = 0.f;
    float msum = 0.f;
    const float* Vb = g_V + ((size_t)bh*LSEQ + ks*KS_KEYS)*DHEAD + d;
    for (int kc = 0; kc < KS_KEYS/4; kc++) {
        float v0 = Vb[(size_t)(kc*4+0)*DHEAD];
        float v1 = Vb[(size_t)(kc*4+1)*DHEAD];
        float v2 = Vb[(size_t)(kc*4+2)*DHEAD];
        float v3 = Vb[(size_t)(kc*4+3)*DHEAD];
        msum += v0 + v1 + v2 + v3;
        #pragma unroll
        for (int i = 0; i < 10; i++) {
            int u = ug*10 + i;
            float4 p4 = *(const float4*)(P + u*KS_KEYS + kc*4);
            acc[i] += p4.x*v0 + p4.y*v1 + p4.z*v2 + p4.w*v3;
        }
    }
    if (ug == 0)
        g_vpart[((size_t)bh*KSPLIT + ks)*DHEAD + d] = msum;
    #pragma unroll
    for (int i = 0; i < 10; i++) {
        int u = ug*10 + i;
        g_pa[(((size_t)(bh*UTOP + u))*KSPLIT + ks)*DHEAD + d] = acc[i];
    }
    if (t < UTOP) {
        g_pm[(bh*UTOP + t)*KSPLIT + ks] = mrow[t];
        g_ps[(bh*UTOP + t)*KSPLIT + ks] = srow[t];
    }
}

__global__ void attn_combine()
{
    int bhu = blockIdx.x;
    int d = threadIdx.x;
    float m = -1e30f;
    #pragma unroll
    for (int j = 0; j < KSPLIT; j++) m = fmaxf(m, g_pm[bhu*KSPLIT + j]);
    float s = 0.f, a = 0.f;
    #pragma unroll
    for (int j = 0; j < KSPLIT; j++) {
        float w = __expf(g_pm[bhu*KSPLIT + j] - m);
        s += w * g_ps[bhu*KSPLIT + j];
        a += w * g_pa[((size_t)bhu*KSPLIT + j)*DHEAD + d];
    }
    g_ctx[(size_t)bhu*DHEAD + d] = a / s;
}

// ================= output-projection compaction =================
__global__ void sel_clear()
{
    int i = blockIdx.x * blockDim.x + threadIdx.x;
    g_selu[i] = 0;
    if (i < BATCH*LSEQ) g_flags[i] = 0;
}
__global__ void sel_mark()
{
    int bh = blockIdx.x, u = threadIdx.x;
    int l = g_top[bh*UTOP + u];
    g_selu[bh*LSEQ + l] = (unsigned char)(u + 1);
    int b_ = bh / NHEAD;
    g_flags[b_*LSEQ + l] = 1;
}
__global__ void compact_kernel()
{
    int b = blockIdx.x, t = threadIdx.x;
    __shared__ int cnts[256];
    __shared__ int l0s;
    int mine[8];
    int cnt = 0;
    #pragma unroll
    for (int j = 0; j < 8; j++) {
        mine[j] = g_flags[b*LSEQ + t*8 + j];
        cnt += mine[j];
    }
    cnts[t] = cnt;
    __syncthreads();
    for (int off = 1; off < 256; off <<= 1) {
        int v = (t >= off) ? cnts[t - off] : 0;
        __syncthreads();
        cnts[t] += v;
        __syncthreads();
    }
    int pos = cnts[t] - cnt;
    int total = cnts[255];
    #pragma unroll
    for (int j = 0; j < 8; j++)
        if (mine[j]) g_rowlist[b*MODROWS + pos++] = t*8 + j;
    __syncthreads();
    if (t == 0) l0s = g_rowlist[b*MODROWS];
    __syncthreads();
    for (int i = total + t; i < MODROWS; i += 256) g_rowlist[b*MODROWS + i] = l0s;
}
__global__ void build_cmod()
{
    int idx = blockIdx.x * blockDim.x + threadIdx.x;
    int d = idx & 1023;
    int r = (idx >> 10) % MODROWS;
    int b = idx / (MODROWS * 1024);
    int l = g_rowlist[b*MODROWS + r];
    int h = d >> 6;
    int bh = b * NHEAD + h;
    unsigned char u = g_selu[bh*LSEQ + l];
    float v = u ? g_ctx[((size_t)bh*UTOP + (u-1))*DHEAD + (d & 63)]
                : g_vmean[bh*DHEAD + (d & 63)];
    __half hi = __float2half(v);
    g_cmh[idx] = hi;
    g_cml[idx] = __float2half(v - __half2float(hi));
}
__global__ void base_out_kernel(const float* __restrict__ Wout, const float* __restrict__ bout)
{
    int gid = blockIdx.x * 8 + (threadIdx.x >> 5);
    int lane = threadIdx.x & 31;
    int b = gid >> 10, n = gid & 1023;
    const float* w = Wout + (size_t)n * DMODEL;
    const float* cb = g_vmean + b * DMODEL;
    float s = 0.f;
    #pragma unroll 8
    for (int k = lane; k < DMODEL; k += 32) s += cb[k] * w[k];
    #pragma unroll
    for (int o = 16; o; o >>= 1) s += __shfl_xor_sync(0xffffffffu, s, o);
    if (lane == 0) g_baseout[b*DMODEL + n] = s + bout[n];
}
__global__ void broadcast_base(float* __restrict__ out)
{
    int idx = blockIdx.x * blockDim.x + threadIdx.x;
    int e = idx * 4;
    int b = e >> 21;
    float4 v = *(const float4*)(g_baseout + b*DMODEL + (e & 1023));
    *(float4*)(out + e) = v;
}

// -----------------------------------------------------------------------------
extern "C" void kernel_launch(void* const* d_in, const int* in_sizes, int n_in,
                              void* d_out, int out_size)
{
    const float* x    = (const float*)d_in[0];
    const float* Wq   = (const float*)d_in[1];
    const float* bq   = (const float*)d_in[2];
    const float* Wkv  = (const float*)d_in[3];
    const float* bkv  = (const float*)d_in[4];
    const float* Wout = (const float*)d_in[5];
    const float* bout = (const float*)d_in[6];
    const int*   idxs = (const int*)d_in[7];
    float* out = (float*)d_out;

    cudaFuncSetAttribute(gemm_tc<0>, cudaFuncAttributeMaxDynamicSharedMemorySize, GSMEM);
    cudaFuncSetAttribute(gemm_tc<1>, cudaFuncAttributeMaxDynamicSharedMemorySize, GSMEM);
    int attn_smem = (UTOP*DHEAD + UTOP*KS_KEYS + 2*UTOP) * sizeof(float);
    cudaFuncSetAttribute(attn_flash, cudaFuncAttributeMaxDynamicSharedMemorySize, attn_smem);

    // conversions
    splitX<<<MROWS*DMODEL/256, 256>>>(x);
    splitWb<<<2*DD/256, 256>>>(Wq, Wkv);
    convH<<<2*DD/256, 256>>>(Wkv, Wout);

    // merged QKV projection: cols 0..15 = QK (bf16 3-pass), 16..23 = V (fp16 2-pass)
    gemm_tc<0><<<dim3(24, MROWS/256), 256, GSMEM>>>(bq, bkv, nullptr);
    // sparsity measure + selection (fp32, 2 l per warp)
    score_m_kernel<<<BHL/16, 256>>>(idxs);
    topk_kernel<<<BATCH*NHEAD, 256>>>();
    // selection maps + compaction
    sel_clear<<<256, 256>>>();
    sel_mark<<<BATCH*NHEAD, UTOP>>>();
    compact_kernel<<<BATCH, 256>>>();
    // flash-split attention (also emits V-mean partials)
    attn_flash<<<dim3(KSPLIT, BATCH*NHEAD), 256, attn_smem>>>();
    vmean_fin<<<BATCH*NHEAD, 64>>>();
    attn_combine<<<BATCH*NHEAD*UTOP, 64>>>();
    // base output rows (exact fp32) + broadcast
    base_out_kernel<<<BATCH*DMODEL/8, 256>>>(Wout, bout);
    broadcast_base<<<MROWS*DMODEL/1024, 256>>>(out);
    // modified context rows -> fp16 split -> scatter GEMM
    build_cmod<<<BATCH*MODROWS*DMODEL/256, 256>>>();
    gemm_tc<1><<<dim3(8, BATCH*MODROWS/256), 256, GSMEM>>>(bout, nullptr, out);
}

// round 12
// speedup vs baseline: 1.0960x; 1.0960x over previous
#include <cuda_runtime.h>
#include <cuda_bf16.h>
#include <cuda_fp16.h>
#include <cstdint>
#include <math.h>

#define BATCH 2
#define LSEQ 2048
#define DMODEL 1024
#define NHEAD 16
#define DHEAD 64
#define UTOP 40
#define MROWS (BATCH*LSEQ)          // 4096
#define BHL (BATCH*NHEAD*LSEQ)      // 65536
#define KSPLIT 8
#define KS_KEYS (LSEQ/KSPLIT)       // 256
#define MODROWS 640
#define DD (DMODEL*DMODEL)

// ---------------- scratch ----------------
__device__ float g_Q[BATCH*NHEAD*LSEQ*DHEAD];
__device__ float g_K[BATCH*NHEAD*LSEQ*DHEAD];
__device__ float g_V[BATCH*NHEAD*LSEQ*DHEAD];
__device__ float g_M[BHL];
__device__ int   g_top[BATCH*NHEAD*UTOP];
__device__ float g_ctx[BATCH*NHEAD*UTOP*DHEAD];
__device__ float g_vpart[BATCH*NHEAD*KSPLIT*DHEAD];
__device__ float g_vmean[BATCH*NHEAD*DHEAD];
__device__ __nv_bfloat16 g_xbh[MROWS*DMODEL], g_xbl[MROWS*DMODEL];
__device__ __half        g_xfh[MROWS*DMODEL], g_xfl[MROWS*DMODEL];
__device__ __nv_bfloat16 g_wbh[2*DD], g_wbl[2*DD];   // [Wq ; Wkv_K] bf16 hi/lo
__device__ __half        g_wv[DD];                   // Wkv_V fp16
__device__ __half        g_wo[DD];                   // Wout fp16
__device__ __half        g_cmh[BATCH*MODROWS*DMODEL], g_cml[BATCH*MODROWS*DMODEL];
__device__ float g_pm[BATCH*NHEAD*UTOP*KSPLIT];
__device__ float g_ps[BATCH*NHEAD*UTOP*KSPLIT];
__device__ float g_pa[BATCH*NHEAD*UTOP*KSPLIT*DHEAD];
__device__ unsigned char g_selu[BATCH*NHEAD*LSEQ];
__device__ int   g_flags[BATCH*LSEQ];
__device__ int   g_rowlist[BATCH*MODROWS];
__device__ float g_baseout[BATCH*DMODEL];

// ================= helpers =================
#define CP_ASYNC16(dst, src) \
    asm volatile("cp.async.cg.shared.global [%0], [%1], 16;" :: "r"(dst), "l"(src))
#define CP_COMMIT() asm volatile("cp.async.commit_group;" ::: "memory")

__device__ __forceinline__ uint32_t smem_u32(const void* p) {
    uint32_t a;
    asm("{ .reg .u64 t; cvta.to.shared.u64 t, %1; cvt.u32.u64 %0, t; }" : "=r"(a) : "l"(p));
    return a;
}
__device__ __forceinline__ void mma_bf(float* c, const uint32_t* a, const uint32_t* b) {
    asm volatile("mma.sync.aligned.m16n8k16.row.col.f32.bf16.bf16.f32 "
        "{%0,%1,%2,%3}, {%4,%5,%6,%7}, {%8,%9}, {%0,%1,%2,%3};"
        : "+f"(c[0]), "+f"(c[1]), "+f"(c[2]), "+f"(c[3])
        : "r"(a[0]), "r"(a[1]), "r"(a[2]), "r"(a[3]), "r"(b[0]), "r"(b[1]));
}
__device__ __forceinline__ void mma_f16(float* c, const uint32_t* a, const uint32_t* b) {
    asm volatile("mma.sync.aligned.m16n8k16.row.col.f32.f16.f16.f32 "
        "{%0,%1,%2,%3}, {%4,%5,%6,%7}, {%8,%9}, {%0,%1,%2,%3};"
        : "+f"(c[0]), "+f"(c[1]), "+f"(c[2]), "+f"(c[3])
        : "r"(a[0]), "r"(a[1]), "r"(a[2]), "r"(a[3]), "r"(b[0]), "r"(b[1]));
}
__device__ __forceinline__ void ldsm_x4(uint32_t* r, uint32_t addr) {
    asm volatile("ldmatrix.sync.aligned.m8n8.x4.shared.b16 {%0,%1,%2,%3}, [%4];"
        : "=r"(r[0]), "=r"(r[1]), "=r"(r[2]), "=r"(r[3]) : "r"(addr));
}
// 64B rows, 4x16B blocks, XOR swizzle by row&3
__device__ __forceinline__ uint32_t sw_addr(uint32_t tile, int row, int cb) {
    return tile + (uint32_t)row * 64 + (uint32_t)((cb ^ (row & 3)) << 4);
}

// ================= conversions =================
__global__ void splitX(const float* __restrict__ src)
{
    int i = blockIdx.x * blockDim.x + threadIdx.x;
    float v = src[i];
    __nv_bfloat16 bh = __float2bfloat16(v);
    g_xbh[i] = bh;
    g_xbl[i] = __float2bfloat16(v - __bfloat162float(bh));
    __half fh = __float2half(v);
    g_xfh[i] = fh;
    g_xfl[i] = __float2half(v - __half2float(fh));
}
__global__ void splitWb(const float* __restrict__ Wq, const float* __restrict__ Wkv)
{
    int i = blockIdx.x * blockDim.x + threadIdx.x;
    float v = (i < DD) ? Wq[i] : Wkv[i - DD];
    __nv_bfloat16 h = __float2bfloat16(v);
    g_wbh[i] = h;
    g_wbl[i] = __float2bfloat16(v - __bfloat162float(h));
}
__global__ void convH(const float* __restrict__ Wkv, const float* __restrict__ Wout)
{
    int i = blockIdx.x * blockDim.x + threadIdx.x;
    if (i < DD) g_wv[i] = __float2half(Wkv[DD + i]);
    else        g_wo[i - DD] = __float2half(Wout[i - DD]);
}

// ================= tensor-core GEMM (R10 tile: 128x128, warp 32x64) ==========
// 8 warps 4x2, K-chunk 32, 3-stage pipeline, XOR-swizzled 64B rows,
// one __syncthreads per chunk, 2 CTAs/SM.
// KIND 0: merged QKV. blockIdx.x 0..15 -> QK (bf16 3-pass),
//                     16..23 -> V (fp16 2-pass, Bl slot unused).
// KIND 1: OUT (Cmod fp16 2-pass, rowlist scatter).
#define TILEB 8192                   // 128 rows x 64B
#define NCHUNK 32
#define NSTAGE 3

template<int KIND>
__global__ void __launch_bounds__(256, 2) gemm_tc(
    const float* __restrict__ bias0, const float* __restrict__ bias1, float* __restrict__ out)
{
    constexpr int NT = (KIND == 0) ? 4 : 3;
    constexpr int STAGE = NT * TILEB;
    extern __shared__ char smem[];
    uint32_t sb = smem_u32(smem);
    const int t = threadIdx.x;
    const int wid = t >> 5;
    const int lane = t & 31;
    const int g  = lane >> 2;
    const int tg = lane & 3;
    const int wm = wid >> 1;
    const int wn = wid & 1;
    const int m0 = blockIdx.y * 128;

    bool qk;
    int n0;
    const char *A0, *A1, *B0, *B1;
    if (KIND == 0) {
        qk = (blockIdx.x < 16);
        n0 = qk ? blockIdx.x * 128 : (blockIdx.x - 16) * 128;
        A0 = qk ? (const char*)g_xbh : (const char*)g_xfh;
        A1 = qk ? (const char*)g_xbl : (const char*)g_xfl;
        B0 = qk ? (const char*)g_wbh : (const char*)g_wv;
        B1 = (const char*)g_wbl;          // only loaded/used when qk
    } else {
        qk = false;
        n0 = blockIdx.x * 128;
        A0 = (const char*)g_cmh; A1 = (const char*)g_cml;
        B0 = (const char*)g_wo;  B1 = nullptr;
    }

    const int arow = lane & 15;
    const int acb  = (lane >> 4) & 1;
    const int brow = (lane & 7) + ((lane >> 4) & 1) * 8;
    const int bcb  = (lane >> 3) & 1;

    float c[2][8][4];
    #pragma unroll
    for (int i = 0; i < 2; i++)
        #pragma unroll
        for (int j = 0; j < 8; j++)
            #pragma unroll
            for (int q = 0; q < 4; q++) c[i][j][q] = 0.f;

    auto load_chunk = [&](uint32_t stage, int kc) {
        int kb = kc * 64;
        #pragma unroll
        for (int r = 0; r < 2; r++) {
            int j   = t + r * 256;
            int row = j >> 2;
            int cb  = j & 3;
            uint32_t d = (uint32_t)row * 64 + (uint32_t)((cb ^ (row & 3)) << 4);
            int off = kb + cb * 16;
            CP_ASYNC16(stage + 0*TILEB + d, A0 + (size_t)(m0 + row) * 2048 + off);
            CP_ASYNC16(stage + 1*TILEB + d, A1 + (size_t)(m0 + row) * 2048 + off);
            CP_ASYNC16(stage + 2*TILEB + d, B0 + (size_t)(n0 + row) * 2048 + off);
            if (KIND == 0) {
                if (qk)
                    CP_ASYNC16(stage + 3*TILEB + d, B1 + (size_t)(n0 + row) * 2048 + off);
            }
        }
    };

    load_chunk(sb, 0);               CP_COMMIT();
    load_chunk(sb + STAGE, 1);       CP_COMMIT();

    int stg = 0;
    for (int kc = 0; kc < NCHUNK; kc++) {
        if (kc < NCHUNK - 1) asm volatile("cp.async.wait_group 1;" ::: "memory");
        else                 asm volatile("cp.async.wait_group 0;" ::: "memory");
        __syncthreads();

        uint32_t Ah = sb + stg * STAGE + 0*TILEB;
        uint32_t Al = sb + stg * STAGE + 1*TILEB;
        uint32_t Bh = sb + stg * STAGE + 2*TILEB;
        uint32_t Bl = Bh + TILEB;

        #pragma unroll
        for (int ks = 0; ks < 2; ks++) {
            uint32_t ah[2][4], al[2][4];
            #pragma unroll
            for (int i = 0; i < 2; i++) {
                int row = wm * 32 + i * 16 + arow;
                int cb  = ks * 2 + acb;
                ldsm_x4(ah[i], sw_addr(Ah, row, cb));
                ldsm_x4(al[i], sw_addr(Al, row, cb));
            }
            #pragma unroll
            for (int jj = 0; jj < 4; jj++) {
                int row = wn * 64 + jj * 16 + brow;
                int cb  = ks * 2 + bcb;
                if (KIND == 0 && qk) {
                    uint32_t bh[4], bl[4];
                    ldsm_x4(bh, sw_addr(Bh, row, cb));
                    ldsm_x4(bl, sw_addr(Bl, row, cb));
                    #pragma unroll
                    for (int i = 0; i < 2; i++) {
                        mma_bf(c[i][2*jj],   ah[i], bh);
                        mma_bf(c[i][2*jj],   ah[i], bl);
                        mma_bf(c[i][2*jj],   al[i], bh);
                        mma_bf(c[i][2*jj+1], ah[i], bh + 2);
                        mma_bf(c[i][2*jj+1], ah[i], bl + 2);
                        mma_bf(c[i][2*jj+1], al[i], bh + 2);
                    }
                } else {
                    uint32_t bq[4];
                    ldsm_x4(bq, sw_addr(Bh, row, cb));
                    #pragma unroll
                    for (int i = 0; i < 2; i++) {
                        mma_f16(c[i][2*jj],   ah[i], bq);
                        mma_f16(c[i][2*jj],   al[i], bq);
                        mma_f16(c[i][2*jj+1], ah[i], bq + 2);
                        mma_f16(c[i][2*jj+1], al[i], bq + 2);
                    }
                }
            }
        }
        if (kc + 2 < NCHUNK) {
            int nstg = stg + 2; if (nstg >= NSTAGE) nstg -= NSTAGE;
            load_chunk(sb + nstg * STAGE, kc + 2);
            CP_COMMIT();
        }
        stg = (stg + 1 == NSTAGE) ? 0 : stg + 1;
    }

    // epilogue
    #pragma unroll
    for (int i = 0; i < 2; i++) {
        #pragma unroll
        for (int j = 0; j < 8; j++) {
            #pragma unroll
            for (int half = 0; half < 2; half++) {
                int m = m0 + wm * 32 + i * 16 + g + half * 8;
                int nl = wn * 64 + j * 8 + 2 * tg;
                float v0 = c[i][j][half*2 + 0];
                float v1 = c[i][j][half*2 + 1];
                if (KIND == 0) {
                    int ncol = blockIdx.x * 128 + nl;     // 0..3071
                    int b_ = m >> 11, l = m & (LSEQ - 1);
                    int which = ncol >> 10;               // 0=Q 1=K 2=V
                    int nloc  = ncol & 1023;
                    int h = nloc >> 6, dh = nloc & 63;
                    const float* bias = (ncol < DMODEL) ? (bias0 + ncol) : (bias1 + ncol - DMODEL);
                    float* dst = (which == 0 ? g_Q : which == 1 ? g_K : g_V)
                               + (((size_t)(b_ * NHEAD + h)) * LSEQ + l) * DHEAD + dh;
                    *(float2*)dst = make_float2(v0 + bias[0], v1 + bias[1]);
                } else {
                    int n = n0 + nl;
                    int b_ = m / MODROWS;
                    int i_ = m - b_ * MODROWS;
                    int l  = g_rowlist[b_ * MODROWS + i_];
                    *(float2*)(out + ((size_t)(b_ * LSEQ + l)) * DMODEL + n) =
                        make_float2(v0 + bias0[n], v1 + bias0[n + 1]);
                }
            }
        }
    }
}

// ================= M scores (fp32, 2 queries per warp) =================
__global__ void score_m_kernel(const int* __restrict__ idxs)
{
    int warp = (blockIdx.x * blockDim.x + threadIdx.x) >> 5;
    int lane = threadIdx.x & 31;
    int bh = warp / (LSEQ/2);
    int l0 = (warp % (LSEQ/2)) * 2;
    const float* qr = g_Q + ((size_t)bh*LSEQ + l0) * DHEAD;
    float qa0 = qr[lane],         qa1 = qr[lane + 32];
    float qb0 = qr[DHEAD + lane], qb1 = qr[DHEAD + lane + 32];
    float mxa = -1e30f, sma = 0.f;
    float mxb = -1e30f, smb = 0.f;
    const float* Kb = g_K + (size_t)bh*LSEQ*DHEAD;
    #pragma unroll 4
    for (int u = 0; u < UTOP; u++) {
        int kia = idxs[l0*UTOP + u];
        int kib = idxs[(l0+1)*UTOP + u];
        const float* kra = Kb + (size_t)kia*DHEAD;
        const float* krb = Kb + (size_t)kib*DHEAD;
        float sa = qa0*kra[lane] + qa1*kra[lane + 32];
        float sb = qb0*krb[lane] + qb1*krb[lane + 32];
        #pragma unroll
        for (int o = 16; o; o >>= 1) {
            sa += __shfl_xor_sync(0xffffffffu, sa, o);
            sb += __shfl_xor_sync(0xffffffffu, sb, o);
        }
        mxa = fmaxf(mxa, sa); sma += sa;
        mxb = fmaxf(mxb, sb); smb += sb;
    }
    if (lane == 0) {
        g_M[(size_t)bh*LSEQ + l0]     = mxa - sma * (1.0f / UTOP);
        g_M[(size_t)bh*LSEQ + l0 + 1] = mxb - smb * (1.0f / UTOP);
    }
}

// ================= top-U =================
__global__ void topk_kernel()
{
    int bh = blockIdx.x;
    __shared__ float vals[LSEQ];
    __shared__ float wv[8];
    __shared__ int   wi[8];
    int t = threadIdx.x, lane = t & 31, wid = t >> 5;
    for (int i = t; i < LSEQ; i += 256) vals[i] = g_M[(size_t)bh*LSEQ + i];
    __syncthreads();
    for (int it = 0; it < UTOP; it++) {
        float v = -2e30f; int bi = 0;
        int base = t * 8;
        #pragma unroll
        for (int j = 0; j < 8; j++) {
            float x = vals[base + j];
            if (x > v) { v = x; bi = base + j; }
        }
        #pragma unroll
        for (int o = 16; o; o >>= 1) {
            float ov = __shfl_xor_sync(0xffffffffu, v, o);
            int   oi = __shfl_xor_sync(0xffffffffu, bi, o);
            if (ov > v) { v = ov; bi = oi; }
        }
        if (lane == 0) { wv[wid] = v; wi[wid] = bi; }
        __syncthreads();
        if (t < 32) {
            float v2 = (t < 8) ? wv[t] : -2e30f;
            int   i2 = (t < 8) ? wi[t] : 0;
            #pragma unroll
            for (int o = 4; o; o >>= 1) {
                float ov = __shfl_xor_sync(0xffffffffu, v2, o);
                int   oi = __shfl_xor_sync(0xffffffffu, i2, o);
                if (ov > v2) { v2 = ov; i2 = oi; }
            }
            if (t == 0) { g_top[bh*UTOP + it] = i2; vals[i2] = -1e30f; }
        }
        __syncthreads();
    }
}

// ================= V mean finish =================
__global__ void vmean_fin()
{
    int bh = blockIdx.x, dh = threadIdx.x;
    float s = 0.f;
    #pragma unroll
    for (int p = 0; p < KSPLIT; p++) s += g_vpart[((size_t)bh*KSPLIT + p)*DHEAD + dh];
    g_vmean[bh*DHEAD + dh] = s * (1.0f / LSEQ);
}

// ================= flash-split attention (+ V-mean partials) =================
__global__ void attn_flash()
{
    extern __shared__ float sm[];
    float* Qt   = sm;
    float* P    = sm + UTOP*DHEAD;
    float* mrow = P + UTOP*KS_KEYS;
    float* srow = mrow + UTOP;
    int ks = blockIdx.x, bh = blockIdx.y;
    int t = threadIdx.x, lane = t & 31, wid = t >> 5;

    for (int i = t; i < UTOP*DHEAD; i += 256) {
        int u = i >> 6, d = i & 63;
        Qt[i] = g_Q[((size_t)bh*LSEQ + g_top[bh*UTOP + u])*DHEAD + d];
    }
    __syncthreads();

    int k = ks * KS_KEYS + t;
    const float4* Kr = (const float4*)(g_K + ((size_t)bh*LSEQ + k)*DHEAD);
    float S[UTOP];
    #pragma unroll
    for (int u = 0; u < UTOP; u++) S[u] = 0.f;
    #pragma unroll
    for (int c = 0; c < 16; c++) {
        float4 kv = Kr[c];
        #pragma unroll
        for (int u = 0; u < UTOP; u++) {
            float4 qv = *(const float4*)(Qt + u*DHEAD + c*4);
            S[u] += kv.x*qv.x + kv.y*qv.y + kv.z*qv.z + kv.w*qv.w;
        }
    }
    #pragma unroll
    for (int u = 0; u < UTOP; u++) P[u*KS_KEYS + t] = S[u] * 0.125f;
    __syncthreads();

    for (int i = 0; i < 5; i++) {
        int u = wid + i*8;
        float* row = P + u*KS_KEYS;
        float m = -1e30f;
        #pragma unroll
        for (int j = 0; j < 8; j++) m = fmaxf(m, row[lane + 32*j]);
        #pragma unroll
        for (int o = 16; o; o >>= 1) m = fmaxf(m, __shfl_xor_sync(0xffffffffu, m, o));
        float s = 0.f;
        #pragma unroll
        for (int j = 0; j < 8; j++) {
            float e = __expf(row[lane + 32*j] - m);
            row[lane + 32*j] = e;
            s += e;
        }
        #pragma unroll
        for (int o = 16; o; o >>= 1) s += __shfl_xor_sync(0xffffffffu, s, o);
        if (lane == 0) { mrow[u] = m; srow[u] = s; }
    }
    __syncthreads();

    int d = t & 63, ug = t >> 6;
    float acc[10];
    #pragma unroll
    for (int i = 0; i < 10; i++) acc[i] = 0.f;
    float msum = 0.f;
    const float* Vb = g_V + ((size_t)bh*LSEQ + ks*KS_KEYS)*DHEAD + d;
    for (int kc = 0; kc < KS_KEYS/4; kc++) {
        float v0 = Vb[(size_t)(kc*4+0)*DHEAD];
        float v1 = Vb[(size_t)(kc*4+1)*DHEAD];
        float v2 = Vb[(size_t)(kc*4+2)*DHEAD];
        float v3 = Vb[(size_t)(kc*4+3)*DHEAD];
        msum += v0 + v1 + v2 + v3;
        #pragma unroll
        for (int i = 0; i < 10; i++) {
            int u = ug*10 + i;
            float4 p4 = *(const float4*)(P + u*KS_KEYS + kc*4);
            acc[i] += p4.x*v0 + p4.y*v1 + p4.z*v2 + p4.w*v3;
        }
    }
    if (ug == 0)
        g_vpart[((size_t)bh*KSPLIT + ks)*DHEAD + d] = msum;
    #pragma unroll
    for (int i = 0; i < 10; i++) {
        int u = ug*10 + i;
        g_pa[(((size_t)(bh*UTOP + u))*KSPLIT + ks)*DHEAD + d] = acc[i];
    }
    if (t < UTOP) {
        g_pm[(bh*UTOP + t)*KSPLIT + ks] = mrow[t];
        g_ps[(bh*UTOP + t)*KSPLIT + ks] = srow[t];
    }
}

__global__ void attn_combine()
{
    int bhu = blockIdx.x;
    int d = threadIdx.x;
    float m = -1e30f;
    #pragma unroll
    for (int j = 0; j < KSPLIT; j++) m = fmaxf(m, g_pm[bhu*KSPLIT + j]);
    float s = 0.f, a = 0.f;
    #pragma unroll
    for (int j = 0; j < KSPLIT; j++) {
        float w = __expf(g_pm[bhu*KSPLIT + j] - m);
        s += w * g_ps[bhu*KSPLIT + j];
        a += w * g_pa[((size_t)bhu*KSPLIT + j)*DHEAD + d];
    }
    g_ctx[(size_t)bhu*DHEAD + d] = a / s;
}

// ================= output-projection compaction =================
__global__ void sel_clear()
{
    int i = blockIdx.x * blockDim.x + threadIdx.x;
    g_selu[i] = 0;
    if (i < BATCH*LSEQ) g_flags[i] = 0;
}
__global__ void sel_mark()
{
    int bh = blockIdx.x, u = threadIdx.x;
    int l = g_top[bh*UTOP + u];
    g_selu[bh*LSEQ + l] = (unsigned char)(u + 1);
    int b_ = bh / NHEAD;
    g_flags[b_*LSEQ + l] = 1;
}
__global__ void compact_kernel()
{
    int b = blockIdx.x, t = threadIdx.x;
    __shared__ int cnts[256];
    __shared__ int l0s;
    int mine[8];
    int cnt = 0;
    #pragma unroll
    for (int j = 0; j < 8; j++) {
        mine[j] = g_flags[b*LSEQ + t*8 + j];
        cnt += mine[j];
    }
    cnts[t] = cnt;
    __syncthreads();
    for (int off = 1; off < 256; off <<= 1) {
        int v = (t >= off) ? cnts[t - off] : 0;
        __syncthreads();
        cnts[t] += v;
        __syncthreads();
    }
    int pos = cnts[t] - cnt;
    int total = cnts[255];
    #pragma unroll
    for (int j = 0; j < 8; j++)
        if (mine[j]) g_rowlist[b*MODROWS + pos++] = t*8 + j;
    __syncthreads();
    if (t == 0) l0s = g_rowlist[b*MODROWS];
    __syncthreads();
    for (int i = total + t; i < MODROWS; i += 256) g_rowlist[b*MODROWS + i] = l0s;
}
__global__ void build_cmod()
{
    int idx = blockIdx.x * blockDim.x + threadIdx.x;
    int d = idx & 1023;
    int r = (idx >> 10) % MODROWS;
    int b = idx / (MODROWS * 1024);
    int l = g_rowlist[b*MODROWS + r];
    int h = d >> 6;
    int bh = b * NHEAD + h;
    unsigned char u = g_selu[bh*LSEQ + l];
    float v = u ? g_ctx[((size_t)bh*UTOP + (u-1))*DHEAD + (d & 63)]
                : g_vmean[bh*DHEAD + (d & 63)];
    __half hi = __float2half(v);
    g_cmh[idx] = hi;
    g_cml[idx] = __float2half(v - __half2float(hi));
}
__global__ void base_out_kernel(const float* __restrict__ Wout, const float* __restrict__ bout)
{
    int gid = blockIdx.x * 8 + (threadIdx.x >> 5);
    int lane = threadIdx.x & 31;
    int b = gid >> 10, n = gid & 1023;
    const float* w = Wout + (size_t)n * DMODEL;
    const float* cb = g_vmean + b * DMODEL;
    float s = 0.f;
    #pragma unroll 8
    for (int k = lane; k < DMODEL; k += 32) s += cb[k] * w[k];
    #pragma unroll
    for (int o = 16; o; o >>= 1) s += __shfl_xor_sync(0xffffffffu, s, o);
    if (lane == 0) g_baseout[b*DMODEL + n] = s + bout[n];
}
__global__ void broadcast_base(float* __restrict__ out)
{
    int idx = blockIdx.x * blockDim.x + threadIdx.x;
    int e = idx * 4;
    int b = e >> 21;
    float4 v = *(const float4*)(g_baseout + b*DMODEL + (e & 1023));
    *(float4*)(out + e) = v;
}

// -----------------------------------------------------------------------------
extern "C" void kernel_launch(void* const* d_in, const int* in_sizes, int n_in,
                              void* d_out, int out_size)
{
    const float* x    = (const float*)d_in[0];
    const float* Wq   = (const float*)d_in[1];
    const float* bq   = (const float*)d_in[2];
    const float* Wkv  = (const float*)d_in[3];
    const float* bkv  = (const float*)d_in[4];
    const float* Wout = (const float*)d_in[5];
    const float* bout = (const float*)d_in[6];
    const int*   idxs = (const int*)d_in[7];
    float* out = (float*)d_out;

    cudaFuncSetAttribute(gemm_tc<0>, cudaFuncAttributeMaxDynamicSharedMemorySize, NSTAGE*4*TILEB);
    cudaFuncSetAttribute(gemm_tc<1>, cudaFuncAttributeMaxDynamicSharedMemorySize, NSTAGE*3*TILEB);
    int attn_smem = (UTOP*DHEAD + UTOP*KS_KEYS + 2*UTOP) * sizeof(float);
    cudaFuncSetAttribute(attn_flash, cudaFuncAttributeMaxDynamicSharedMemorySize, attn_smem);

    // conversions
    splitX<<<MROWS*DMODEL/256, 256>>>(x);
    splitWb<<<2*DD/256, 256>>>(Wq, Wkv);
    convH<<<2*DD/256, 256>>>(Wkv, Wout);

    // merged QKV projection: cols 0..15 = QK (bf16 3-pass), 16..23 = V (fp16 2-pass)
    gemm_tc<0><<<dim3(24, MROWS/128), 256, NSTAGE*4*TILEB>>>(bq, bkv, nullptr);
    // sparsity measure + selection (fp32, 2 l per warp)
    score_m_kernel<<<BHL/16, 256>>>(idxs);
    topk_kernel<<<BATCH*NHEAD, 256>>>();
    // selection maps + compaction
    sel_clear<<<256, 256>>>();
    sel_mark<<<BATCH*NHEAD, UTOP>>>();
    compact_kernel<<<BATCH, 256>>>();
    // flash-split attention (also emits V-mean partials)
    attn_flash<<<dim3(KSPLIT, BATCH*NHEAD), 256, attn_smem>>>();
    vmean_fin<<<BATCH*NHEAD, 64>>>();
    attn_combine<<<BATCH*NHEAD*UTOP, 64>>>();
    // base output rows (exact fp32) + broadcast
    base_out_kernel<<<BATCH*DMODEL/8, 256>>>(Wout, bout);
    broadcast_base<<<MROWS*DMODEL/1024, 256>>>(out);
    // modified context rows -> fp16 split -> scatter GEMM
    build_cmod<<<BATCH*MODROWS*DMODEL/256, 256>>>();
    gemm_tc<1><<<dim3(8, BATCH*MODROWS/128), 256, NSTAGE*3*TILEB>>>(bout, nullptr, out);
}

// round 13
// speedup vs baseline: 1.1298x; 1.0308x over previous
#include <cuda_runtime.h>
#include <cuda_bf16.h>
#include <cuda_fp16.h>
#include <cstdint>
#include <math.h>

#define BATCH 2
#define LSEQ 2048
#define DMODEL 1024
#define NHEAD 16
#define DHEAD 64
#define UTOP 40
#define MROWS (BATCH*LSEQ)          // 4096
#define BHL (BATCH*NHEAD*LSEQ)      // 65536
#define KSPLIT 8
#define KS_KEYS (LSEQ/KSPLIT)       // 256
#define MODROWS 640
#define DD (DMODEL*DMODEL)

// ---------------- scratch ----------------
__device__ float g_Q[BATCH*NHEAD*LSEQ*DHEAD];
__device__ float g_K[BATCH*NHEAD*LSEQ*DHEAD];
__device__ float g_V[BATCH*NHEAD*LSEQ*DHEAD];
__device__ float g_M[BHL];
__device__ int   g_top[BATCH*NHEAD*UTOP];
__device__ float g_ctx[BATCH*NHEAD*UTOP*DHEAD];
__device__ float g_vpart[BATCH*NHEAD*KSPLIT*DHEAD];
__device__ float g_vmean[BATCH*NHEAD*DHEAD];
__device__ __nv_bfloat16 g_xbh[MROWS*DMODEL], g_xbl[MROWS*DMODEL];
__device__ __half        g_xfh[MROWS*DMODEL], g_xfl[MROWS*DMODEL];
__device__ __nv_bfloat16 g_wbh[2*DD], g_wbl[2*DD];   // [Wq ; Wkv_K] bf16 hi/lo
__device__ __half        g_wv[DD];                   // Wkv_V fp16
__device__ __half        g_wo[DD];                   // Wout fp16
__device__ __half        g_cmh[BATCH*MODROWS*DMODEL], g_cml[BATCH*MODROWS*DMODEL];
__device__ float g_pm[BATCH*NHEAD*UTOP*KSPLIT];
__device__ float g_ps[BATCH*NHEAD*UTOP*KSPLIT];
__device__ float g_pa[BATCH*NHEAD*UTOP*KSPLIT*DHEAD];
__device__ unsigned char g_selu[BATCH*NHEAD*LSEQ];
__device__ int   g_flags[BATCH*LSEQ];
__device__ int   g_rowlist[BATCH*MODROWS];
__device__ float g_baseout[BATCH*DMODEL];

// ================= helpers =================
#define CP_ASYNC16(dst, src) \
    asm volatile("cp.async.cg.shared.global [%0], [%1], 16;" :: "r"(dst), "l"(src))
#define CP_COMMIT() asm volatile("cp.async.commit_group;" ::: "memory")

__device__ __forceinline__ uint32_t smem_u32(const void* p) {
    uint32_t a;
    asm("{ .reg .u64 t; cvta.to.shared.u64 t, %1; cvt.u32.u64 %0, t; }" : "=r"(a) : "l"(p));
    return a;
}
__device__ __forceinline__ void mma_bf(float* c, const uint32_t* a, const uint32_t* b) {
    asm volatile("mma.sync.aligned.m16n8k16.row.col.f32.bf16.bf16.f32 "
        "{%0,%1,%2,%3}, {%4,%5,%6,%7}, {%8,%9}, {%0,%1,%2,%3};"
        : "+f"(c[0]), "+f"(c[1]), "+f"(c[2]), "+f"(c[3])
        : "r"(a[0]), "r"(a[1]), "r"(a[2]), "r"(a[3]), "r"(b[0]), "r"(b[1]));
}
__device__ __forceinline__ void mma_f16(float* c, const uint32_t* a, const uint32_t* b) {
    asm volatile("mma.sync.aligned.m16n8k16.row.col.f32.f16.f16.f32 "
        "{%0,%1,%2,%3}, {%4,%5,%6,%7}, {%8,%9}, {%0,%1,%2,%3};"
        : "+f"(c[0]), "+f"(c[1]), "+f"(c[2]), "+f"(c[3])
        : "r"(a[0]), "r"(a[1]), "r"(a[2]), "r"(a[3]), "r"(b[0]), "r"(b[1]));
}
__device__ __forceinline__ void ldsm_x4(uint32_t* r, uint32_t addr) {
    asm volatile("ldmatrix.sync.aligned.m8n8.x4.shared.b16 {%0,%1,%2,%3}, [%4];"
        : "=r"(r[0]), "=r"(r[1]), "=r"(r[2]), "=r"(r[3]) : "r"(addr));
}
// 64B rows, 4x16B blocks, XOR swizzle by row&3
__device__ __forceinline__ uint32_t sw_addr(uint32_t tile, int row, int cb) {
    return tile + (uint32_t)row * 64 + (uint32_t)((cb ^ (row & 3)) << 4);
}

// ================= conversions =================
__global__ void splitX(const float* __restrict__ src)
{
    int i = blockIdx.x * blockDim.x + threadIdx.x;
    float v = src[i];
    __nv_bfloat16 bh = __float2bfloat16(v);
    g_xbh[i] = bh;
    g_xbl[i] = __float2bfloat16(v - __bfloat162float(bh));
    __half fh = __float2half(v);
    g_xfh[i] = fh;
    g_xfl[i] = __float2half(v - __half2float(fh));
}
__global__ void splitWb(const float* __restrict__ Wq, const float* __restrict__ Wkv)
{
    int i = blockIdx.x * blockDim.x + threadIdx.x;
    float v = (i < DD) ? Wq[i] : Wkv[i - DD];
    __nv_bfloat16 h = __float2bfloat16(v);
    g_wbh[i] = h;
    g_wbl[i] = __float2bfloat16(v - __bfloat162float(h));
}
__global__ void convH(const float* __restrict__ Wkv, const float* __restrict__ Wout)
{
    int i = blockIdx.x * blockDim.x + threadIdx.x;
    if (i < DD) g_wv[i] = __float2half(Wkv[DD + i]);
    else        g_wo[i - DD] = __float2half(Wout[i - DD]);
}

// ================= tensor-core GEMM (R10: 128x128 tile, warp 32x64) ==========
// 8 warps 4x2, K-chunk 32, 3-stage pipeline, XOR-swizzled 64B rows,
// one __syncthreads per chunk, 2 CTAs/SM.
// MODE 0: QK bf16 3-pass (N=2048), MODE 1: V fp16 2-pass, MODE 2: OUT fp16 2-pass.
#define TILEB 8192                   // 128 rows x 64B
#define NCHUNK 32
#define NSTAGE 3

template<int MODE>
__global__ void __launch_bounds__(256, 2) gemm_tc(
    const float* __restrict__ bias0, const float* __restrict__ bias1, float* __restrict__ out)
{
    constexpr int NT = (MODE == 0) ? 4 : 3;
    constexpr int STAGE = NT * TILEB;
    extern __shared__ char smem[];
    uint32_t sb = smem_u32(smem);
    const int t = threadIdx.x;
    const int wid = t >> 5;
    const int lane = t & 31;
    const int g  = lane >> 2;
    const int tg = lane & 3;
    const int wm = wid >> 1;
    const int wn = wid & 1;
    const int m0 = blockIdx.y * 128;
    const int n0 = blockIdx.x * 128;

    const char *A0, *A1, *B0, *B1 = nullptr;
    if (MODE == 0) { A0 = (const char*)g_xbh; A1 = (const char*)g_xbl;
                     B0 = (const char*)g_wbh; B1 = (const char*)g_wbl; }
    else if (MODE == 1) { A0 = (const char*)g_xfh; A1 = (const char*)g_xfl;
                          B0 = (const char*)g_wv; }
    else { A0 = (const char*)g_cmh; A1 = (const char*)g_cml;
           B0 = (const char*)g_wo; }

    const int arow = lane & 15;
    const int acb  = (lane >> 4) & 1;
    const int brow = (lane & 7) + ((lane >> 4) & 1) * 8;
    const int bcb  = (lane >> 3) & 1;

    float c[2][8][4];
    #pragma unroll
    for (int i = 0; i < 2; i++)
        #pragma unroll
        for (int j = 0; j < 8; j++)
            #pragma unroll
            for (int q = 0; q < 4; q++) c[i][j][q] = 0.f;

    auto load_chunk = [&](uint32_t stage, int kc) {
        int kb = kc * 64;
        #pragma unroll
        for (int r = 0; r < 2; r++) {
            int j   = t + r * 256;
            int row = j >> 2;
            int cb  = j & 3;
            uint32_t d = (uint32_t)row * 64 + (uint32_t)((cb ^ (row & 3)) << 4);
            int off = kb + cb * 16;
            CP_ASYNC16(stage + 0*TILEB + d, A0 + (size_t)(m0 + row) * 2048 + off);
            CP_ASYNC16(stage + 1*TILEB + d, A1 + (size_t)(m0 + row) * 2048 + off);
            CP_ASYNC16(stage + 2*TILEB + d, B0 + (size_t)(n0 + row) * 2048 + off);
            if (NT == 4)
                CP_ASYNC16(stage + 3*TILEB + d, B1 + (size_t)(n0 + row) * 2048 + off);
        }
    };

    load_chunk(sb, 0);               CP_COMMIT();
    load_chunk(sb + STAGE, 1);       CP_COMMIT();

    int stg = 0;
    for (int kc = 0; kc < NCHUNK; kc++) {
        if (kc < NCHUNK - 1) asm volatile("cp.async.wait_group 1;" ::: "memory");
        else                 asm volatile("cp.async.wait_group 0;" ::: "memory");
        __syncthreads();

        uint32_t Ah = sb + stg * STAGE + 0*TILEB;
        uint32_t Al = sb + stg * STAGE + 1*TILEB;
        uint32_t Bh = sb + stg * STAGE + 2*TILEB;
        uint32_t Bl = Bh + TILEB;

        #pragma unroll
        for (int ks = 0; ks < 2; ks++) {
            uint32_t ah[2][4], al[2][4];
            #pragma unroll
            for (int i = 0; i < 2; i++) {
                int row = wm * 32 + i * 16 + arow;
                int cb  = ks * 2 + acb;
                ldsm_x4(ah[i], sw_addr(Ah, row, cb));
                ldsm_x4(al[i], sw_addr(Al, row, cb));
            }
            #pragma unroll
            for (int jj = 0; jj < 4; jj++) {
                int row = wn * 64 + jj * 16 + brow;
                int cb  = ks * 2 + bcb;
                if (MODE == 0) {
                    uint32_t bh[4], bl[4];
                    ldsm_x4(bh, sw_addr(Bh, row, cb));
                    ldsm_x4(bl, sw_addr(Bl, row, cb));
                    #pragma unroll
                    for (int i = 0; i < 2; i++) {
                        mma_bf(c[i][2*jj],   ah[i], bh);
                        mma_bf(c[i][2*jj],   ah[i], bl);
                        mma_bf(c[i][2*jj],   al[i], bh);
                        mma_bf(c[i][2*jj+1], ah[i], bh + 2);
                        mma_bf(c[i][2*jj+1], ah[i], bl + 2);
                        mma_bf(c[i][2*jj+1], al[i], bh + 2);
                    }
                } else {
                    uint32_t bq[4];
                    ldsm_x4(bq, sw_addr(Bh, row, cb));
                    #pragma unroll
                    for (int i = 0; i < 2; i++) {
                        mma_f16(c[i][2*jj],   ah[i], bq);
                        mma_f16(c[i][2*jj],   al[i], bq);
                        mma_f16(c[i][2*jj+1], ah[i], bq + 2);
                        mma_f16(c[i][2*jj+1], al[i], bq + 2);
                    }
                }
            }
        }
        if (kc + 2 < NCHUNK) {
            int nstg = stg + 2; if (nstg >= NSTAGE) nstg -= NSTAGE;
            load_chunk(sb + nstg * STAGE, kc + 2);
            CP_COMMIT();
        }
        stg = (stg + 1 == NSTAGE) ? 0 : stg + 1;
    }

    // epilogue
    #pragma unroll
    for (int i = 0; i < 2; i++) {
        #pragma unroll
        for (int j = 0; j < 8; j++) {
            #pragma unroll
            for (int half = 0; half < 2; half++) {
                int m = m0 + wm * 32 + i * 16 + g + half * 8;
                int n = n0 + wn * 64 + j * 8 + 2 * tg;
                float v0 = c[i][j][half*2 + 0];
                float v1 = c[i][j][half*2 + 1];
                if (MODE == 0) {
                    int b_ = m >> 11, l = m & (LSEQ - 1);
                    int nloc = n & 1023;
                    int h = nloc >> 6, dh = nloc & 63;
                    const float* bias = (n < DMODEL) ? (bias0 + n) : (bias1 + n - DMODEL);
                    float* dst = ((n < DMODEL) ? g_Q : g_K)
                               + (((size_t)(b_ * NHEAD + h)) * LSEQ + l) * DHEAD + dh;
                    *(float2*)dst = make_float2(v0 + bias[0], v1 + bias[1]);
                } else if (MODE == 1) {
                    int b_ = m >> 11, l = m & (LSEQ - 1);
                    int h = n >> 6, dh = n & 63;
                    const float* bias = bias1 + DMODEL + n;
                    float* dst = g_V + (((size_t)(b_ * NHEAD + h)) * LSEQ + l) * DHEAD + dh;
                    *(float2*)dst = make_float2(v0 + bias[0], v1 + bias[1]);
                } else {
                    int b_ = m / MODROWS;
                    int i_ = m - b_ * MODROWS;
                    int l  = g_rowlist[b_ * MODROWS + i_];
                    *(float2*)(out + ((size_t)(b_ * LSEQ + l)) * DMODEL + n) =
                        make_float2(v0 + bias0[n], v1 + bias0[n + 1]);
                }
            }
        }
    }
}

// ================= M scores (fp32, 2 queries per warp) =================
__global__ void score_m_kernel(const int* __restrict__ idxs)
{
    int warp = (blockIdx.x * blockDim.x + threadIdx.x) >> 5;
    int lane = threadIdx.x & 31;
    int bh = warp / (LSEQ/2);
    int l0 = (warp % (LSEQ/2)) * 2;
    const float* qr = g_Q + ((size_t)bh*LSEQ + l0) * DHEAD;
    float qa0 = qr[lane],         qa1 = qr[lane + 32];
    float qb0 = qr[DHEAD + lane], qb1 = qr[DHEAD + lane + 32];
    float mxa = -1e30f, sma = 0.f;
    float mxb = -1e30f, smb = 0.f;
    const float* Kb = g_K + (size_t)bh*LSEQ*DHEAD;
    #pragma unroll 4
    for (int u = 0; u < UTOP; u++) {
        int kia = idxs[l0*UTOP + u];
        int kib = idxs[(l0+1)*UTOP + u];
        const float* kra = Kb + (size_t)kia*DHEAD;
        const float* krb = Kb + (size_t)kib*DHEAD;
        float sa = qa0*kra[lane] + qa1*kra[lane + 32];
        float sb = qb0*krb[lane] + qb1*krb[lane + 32];
        #pragma unroll
        for (int o = 16; o; o >>= 1) {
            sa += __shfl_xor_sync(0xffffffffu, sa, o);
            sb += __shfl_xor_sync(0xffffffffu, sb, o);
        }
        mxa = fmaxf(mxa, sa); sma += sa;
        mxb = fmaxf(mxb, sb); smb += sb;
    }
    if (lane == 0) {
        g_M[(size_t)bh*LSEQ + l0]     = mxa - sma * (1.0f / UTOP);
        g_M[(size_t)bh*LSEQ + l0 + 1] = mxb - smb * (1.0f / UTOP);
    }
}

// ================= top-U =================
__global__ void topk_kernel()
{
    int bh = blockIdx.x;
    __shared__ float vals[LSEQ];
    __shared__ float wv[8];
    __shared__ int   wi[8];
    int t = threadIdx.x, lane = t & 31, wid = t >> 5;
    for (int i = t; i < LSEQ; i += 256) vals[i] = g_M[(size_t)bh*LSEQ + i];
    __syncthreads();
    for (int it = 0; it < UTOP; it++) {
        float v = -2e30f; int bi = 0;
        int base = t * 8;
        #pragma unroll
        for (int j = 0; j < 8; j++) {
            float x = vals[base + j];
            if (x > v) { v = x; bi = base + j; }
        }
        #pragma unroll
        for (int o = 16; o; o >>= 1) {
            float ov = __shfl_xor_sync(0xffffffffu, v, o);
            int   oi = __shfl_xor_sync(0xffffffffu, bi, o);
            if (ov > v) { v = ov; bi = oi; }
        }
        if (lane == 0) { wv[wid] = v; wi[wid] = bi; }
        __syncthreads();
        if (t < 32) {
            float v2 = (t < 8) ? wv[t] : -2e30f;
            int   i2 = (t < 8) ? wi[t] : 0;
            #pragma unroll
            for (int o = 4; o; o >>= 1) {
                float ov = __shfl_xor_sync(0xffffffffu, v2, o);
                int   oi = __shfl_xor_sync(0xffffffffu, i2, o);
                if (ov > v2) { v2 = ov; i2 = oi; }
            }
            if (t == 0) { g_top[bh*UTOP + it] = i2; vals[i2] = -1e30f; }
        }
        __syncthreads();
    }
}

// ================= V mean finish =================
__global__ void vmean_fin()
{
    int bh = blockIdx.x, dh = threadIdx.x;
    float s = 0.f;
    #pragma unroll
    for (int p = 0; p < KSPLIT; p++) s += g_vpart[((size_t)bh*KSPLIT + p)*DHEAD + dh];
    g_vmean[bh*DHEAD + dh] = s * (1.0f / LSEQ);
}

// ================= flash-split attention (+ V-mean partials) =================
__global__ void attn_flash()
{
    extern __shared__ float sm[];
    float* Qt   = sm;
    float* P    = sm + UTOP*DHEAD;
    float* mrow = P + UTOP*KS_KEYS;
    float* srow = mrow + UTOP;
    int ks = blockIdx.x, bh = blockIdx.y;
    int t = threadIdx.x, lane = t & 31, wid = t >> 5;

    for (int i = t; i < UTOP*DHEAD; i += 256) {
        int u = i >> 6, d = i & 63;
        Qt[i] = g_Q[((size_t)bh*LSEQ + g_top[bh*UTOP + u])*DHEAD + d];
    }
    __syncthreads();

    int k = ks * KS_KEYS + t;
    const float4* Kr = (const float4*)(g_K + ((size_t)bh*LSEQ + k)*DHEAD);
    float S[UTOP];
    #pragma unroll
    for (int u = 0; u < UTOP; u++) S[u] = 0.f;
    #pragma unroll
    for (int c = 0; c < 16; c++) {
        float4 kv = Kr[c];
        #pragma unroll
        for (int u = 0; u < UTOP; u++) {
            float4 qv = *(const float4*)(Qt + u*DHEAD + c*4);
            S[u] += kv.x*qv.x + kv.y*qv.y + kv.z*qv.z + kv.w*qv.w;
        }
    }
    #pragma unroll
    for (int u = 0; u < UTOP; u++) P[u*KS_KEYS + t] = S[u] * 0.125f;
    __syncthreads();

    for (int i = 0; i < 5; i++) {
        int u = wid + i*8;
        float* row = P + u*KS_KEYS;
        float m = -1e30f;
        #pragma unroll
        for (int j = 0; j < 8; j++) m = fmaxf(m, row[lane + 32*j]);
        #pragma unroll
        for (int o = 16; o; o >>= 1) m = fmaxf(m, __shfl_xor_sync(0xffffffffu, m, o));
        float s = 0.f;
        #pragma unroll
        for (int j = 0; j < 8; j++) {
            float e = __expf(row[lane + 32*j] - m);
            row[lane + 32*j] = e;
            s += e;
        }
        #pragma unroll
        for (int o = 16; o; o >>= 1) s += __shfl_xor_sync(0xffffffffu, s, o);
        if (lane == 0) { mrow[u] = m; srow[u] = s; }
    }
    __syncthreads();

    int d = t & 63, ug = t >> 6;
    float acc[10];
    #pragma unroll
    for (int i = 0; i < 10; i++) acc[i] = 0.f;
    float msum = 0.f;
    const float* Vb = g_V + ((size_t)bh*LSEQ + ks*KS_KEYS)*DHEAD + d;
    for (int kc = 0; kc < KS_KEYS/4; kc++) {
        float v0 = Vb[(size_t)(kc*4+0)*DHEAD];
        float v1 = Vb[(size_t)(kc*4+1)*DHEAD];
        float v2 = Vb[(size_t)(kc*4+2)*DHEAD];
        float v3 = Vb[(size_t)(kc*4+3)*DHEAD];
        msum += v0 + v1 + v2 + v3;
        #pragma unroll
        for (int i = 0; i < 10; i++) {
            int u = ug*10 + i;
            float4 p4 = *(const float4*)(P + u*KS_KEYS + kc*4);
            acc[i] += p4.x*v0 + p4.y*v1 + p4.z*v2 + p4.w*v3;
        }
    }
    if (ug == 0)
        g_vpart[((size_t)bh*KSPLIT + ks)*DHEAD + d] = msum;
    #pragma unroll
    for (int i = 0; i < 10; i++) {
        int u = ug*10 + i;
        g_pa[(((size_t)(bh*UTOP + u))*KSPLIT + ks)*DHEAD + d] = acc[i];
    }
    if (t < UTOP) {
        g_pm[(bh*UTOP + t)*KSPLIT + ks] = mrow[t];
        g_ps[(bh*UTOP + t)*KSPLIT + ks] = srow[t];
    }
}

__global__ void attn_combine()
{
    int bhu = blockIdx.x;
    int d = threadIdx.x;
    float m = -1e30f;
    #pragma unroll
    for (int j = 0; j < KSPLIT; j++) m = fmaxf(m, g_pm[bhu*KSPLIT + j]);
    float s = 0.f, a = 0.f;
    #pragma unroll
    for (int j = 0; j < KSPLIT; j++) {
        float w = __expf(g_pm[bhu*KSPLIT + j] - m);
        s += w * g_ps[bhu*KSPLIT + j];
        a += w * g_pa[((size_t)bhu*KSPLIT + j)*DHEAD + d];
    }
    g_ctx[(size_t)bhu*DHEAD + d] = a / s;
}

// ================= output-projection compaction =================
__global__ void sel_clear()
{
    int i = blockIdx.x * blockDim.x + threadIdx.x;
    g_selu[i] = 0;
    if (i < BATCH*LSEQ) g_flags[i] = 0;
}
__global__ void sel_mark()
{
    int bh = blockIdx.x, u = threadIdx.x;
    int l = g_top[bh*UTOP + u];
    g_selu[bh*LSEQ + l] = (unsigned char)(u + 1);
    int b_ = bh / NHEAD;
    g_flags[b_*LSEQ + l] = 1;
}
__global__ void compact_kernel()
{
    int b = blockIdx.x, t = threadIdx.x;
    __shared__ int cnts[256];
    __shared__ int l0s;
    int mine[8];
    int cnt = 0;
    #pragma unroll
    for (int j = 0; j < 8; j++) {
        mine[j] = g_flags[b*LSEQ + t*8 + j];
        cnt += mine[j];
    }
    cnts[t] = cnt;
    __syncthreads();
    for (int off = 1; off < 256; off <<= 1) {
        int v = (t >= off) ? cnts[t - off] : 0;
        __syncthreads();
        cnts[t] += v;
        __syncthreads();
    }
    int pos = cnts[t] - cnt;
    int total = cnts[255];
    #pragma unroll
    for (int j = 0; j < 8; j++)
        if (mine[j]) g_rowlist[b*MODROWS + pos++] = t*8 + j;
    __syncthreads();
    if (t == 0) l0s = g_rowlist[b*MODROWS];
    __syncthreads();
    for (int i = total + t; i < MODROWS; i += 256) g_rowlist[b*MODROWS + i] = l0s;
}
__global__ void build_cmod()
{
    int idx = blockIdx.x * blockDim.x + threadIdx.x;
    int d = idx & 1023;
    int r = (idx >> 10) % MODROWS;
    int b = idx / (MODROWS * 1024);
    int l = g_rowlist[b*MODROWS + r];
    int h = d >> 6;
    int bh = b * NHEAD + h;
    unsigned char u = g_selu[bh*LSEQ + l];
    float v = u ? g_ctx[((size_t)bh*UTOP + (u-1))*DHEAD + (d & 63)]
                : g_vmean[bh*DHEAD + (d & 63)];
    __half hi = __float2half(v);
    g_cmh[idx] = hi;
    g_cml[idx] = __float2half(v - __half2float(hi));
}
__global__ void base_out_kernel(const float* __restrict__ Wout, const float* __restrict__ bout)
{
    int gid = blockIdx.x * 8 + (threadIdx.x >> 5);
    int lane = threadIdx.x & 31;
    int b = gid >> 10, n = gid & 1023;
    const float* w = Wout + (size_t)n * DMODEL;
    const float* cb = g_vmean + b * DMODEL;
    float s = 0.f;
    #pragma unroll 8
    for (int k = lane; k < DMODEL; k += 32) s += cb[k] * w[k];
    #pragma unroll
    for (int o = 16; o; o >>= 1) s += __shfl_xor_sync(0xffffffffu, s, o);
    if (lane == 0) g_baseout[b*DMODEL + n] = s + bout[n];
}
__global__ void broadcast_base(float* __restrict__ out)
{
    int idx = blockIdx.x * blockDim.x + threadIdx.x;
    int e = idx * 4;
    int b = e >> 21;
    float4 v = *(const float4*)(g_baseout + b*DMODEL + (e & 1023));
    *(float4*)(out + e) = v;
}

// -----------------------------------------------------------------------------
extern "C" void kernel_launch(void* const* d_in, const int* in_sizes, int n_in,
                              void* d_out, int out_size)
{
    const float* x    = (const float*)d_in[0];
    const float* Wq   = (const float*)d_in[1];
    const float* bq   = (const float*)d_in[2];
    const float* Wkv  = (const float*)d_in[3];
    const float* bkv  = (const float*)d_in[4];
    const float* Wout = (const float*)d_in[5];
    const float* bout = (const float*)d_in[6];
    const int*   idxs = (const int*)d_in[7];
    float* out = (float*)d_out;

    cudaFuncSetAttribute(gemm_tc<0>, cudaFuncAttributeMaxDynamicSharedMemorySize, NSTAGE*4*TILEB);
    cudaFuncSetAttribute(gemm_tc<1>, cudaFuncAttributeMaxDynamicSharedMemorySize, NSTAGE*3*TILEB);
    cudaFuncSetAttribute(gemm_tc<2>, cudaFuncAttributeMaxDynamicSharedMemorySize, NSTAGE*3*TILEB);
    int attn_smem = (UTOP*DHEAD + UTOP*KS_KEYS + 2*UTOP) * sizeof(float);
    cudaFuncSetAttribute(attn_flash, cudaFuncAttributeMaxDynamicSharedMemorySize, attn_smem);

    // side stream + fork/join events (host-side objects; no device allocation)
    cudaStream_t s1;
    cudaStreamCreateWithFlags(&s1, cudaStreamNonBlocking);
    cudaEvent_t evF, evJ, evF2, evJ2;
    cudaEventCreateWithFlags(&evF,  cudaEventDisableTiming);
    cudaEventCreateWithFlags(&evJ,  cudaEventDisableTiming);
    cudaEventCreateWithFlags(&evF2, cudaEventDisableTiming);
    cudaEventCreateWithFlags(&evJ2, cudaEventDisableTiming);

    // conversions (origin stream)
    splitX<<<MROWS*DMODEL/256, 256>>>(x);
    splitWb<<<2*DD/256, 256>>>(Wq, Wkv);
    convH<<<2*DD/256, 256>>>(Wkv, Wout);
    sel_clear<<<256, 256>>>();

    // fork: V projection on s1, QK + selection chain on origin
    cudaEventRecord(evF, 0);
    cudaStreamWaitEvent(s1, evF, 0);
    gemm_tc<1><<<dim3(DMODEL/128, MROWS/128), 256, NSTAGE*3*TILEB, s1>>>(nullptr, bkv, nullptr);
    cudaEventRecord(evJ, s1);

    gemm_tc<0><<<dim3(2*DMODEL/128, MROWS/128), 256, NSTAGE*4*TILEB>>>(bq, bkv, nullptr);
    score_m_kernel<<<BHL/16, 256>>>(idxs);
    topk_kernel<<<BATCH*NHEAD, 256>>>();
    sel_mark<<<BATCH*NHEAD, UTOP>>>();
    compact_kernel<<<BATCH, 256>>>();

    // join: attention needs V + selection
    cudaStreamWaitEvent(0, evJ, 0);
    attn_flash<<<dim3(KSPLIT, BATCH*NHEAD), 256, attn_smem>>>();
    vmean_fin<<<BATCH*NHEAD, 64>>>();

    // fork 2: base rows + broadcast on s1; ctx combine + cmod on origin
    cudaEventRecord(evF2, 0);
    cudaStreamWaitEvent(s1, evF2, 0);
    base_out_kernel<<<BATCH*DMODEL/8, 256, 0, s1>>>(Wout, bout);
    broadcast_base<<<MROWS*DMODEL/1024, 256, 0, s1>>>(out);
    cudaEventRecord(evJ2, s1);

    attn_combine<<<BATCH*NHEAD*UTOP, 64>>>();
    build_cmod<<<BATCH*MODROWS*DMODEL/256, 256>>>();

    // join: scatter GEMM must follow the broadcast it overwrites
    cudaStreamWaitEvent(0, evJ2, 0);
    gemm_tc<2><<<dim3(8, BATCH*MODROWS/128), 256, NSTAGE*3*TILEB>>>(bout, nullptr, out);
}

// round 14
// speedup vs baseline: 1.1943x; 1.0571x over previous
#include <cuda_runtime.h>
#include <cuda_bf16.h>
#include <cuda_fp16.h>
#include <cstdint>
#include <math.h>

#define BATCH 2
#define LSEQ 2048
#define DMODEL 1024
#define NHEAD 16
#define DHEAD 64
#define UTOP 40
#define MROWS (BATCH*LSEQ)          // 4096
#define BHL (BATCH*NHEAD*LSEQ)      // 65536
#define KSPLIT 8
#define KS_KEYS (LSEQ/KSPLIT)       // 256
#define MODROWS 640
#define DD (DMODEL*DMODEL)

// ---------------- scratch ----------------
__device__ float g_Q[BATCH*NHEAD*LSEQ*DHEAD];
__device__ float g_K[BATCH*NHEAD*LSEQ*DHEAD];
__device__ float g_V[BATCH*NHEAD*LSEQ*DHEAD];
__device__ float g_M[BHL];
__device__ int   g_top[BATCH*NHEAD*UTOP];
__device__ float g_ctx[BATCH*NHEAD*UTOP*DHEAD];
__device__ float g_vpart[BATCH*NHEAD*KSPLIT*DHEAD];
__device__ float g_vmean[BATCH*NHEAD*DHEAD];
__device__ __nv_bfloat16 g_xbh[MROWS*DMODEL], g_xbl[MROWS*DMODEL];
__device__ __half        g_xfh[MROWS*DMODEL], g_xfl[MROWS*DMODEL];
__device__ __nv_bfloat16 g_wbh[2*DD], g_wbl[2*DD];   // [Wq ; Wkv_K] bf16 hi/lo
__device__ __half        g_wv[DD];                   // Wkv_V fp16
__device__ __half        g_wo[DD];                   // Wout fp16
__device__ __half        g_cmh[BATCH*MODROWS*DMODEL], g_cml[BATCH*MODROWS*DMODEL];
__device__ float g_pm[BATCH*NHEAD*UTOP*KSPLIT];
__device__ float g_ps[BATCH*NHEAD*UTOP*KSPLIT];
__device__ float g_pa[BATCH*NHEAD*UTOP*KSPLIT*DHEAD];
__device__ unsigned char g_selu[BATCH*NHEAD*LSEQ];
__device__ int   g_flags[BATCH*LSEQ];
__device__ int   g_rowlist[BATCH*MODROWS];
__device__ float g_baseout[BATCH*DMODEL];

// ================= helpers =================
#define CP_ASYNC16(dst, src) \
    asm volatile("cp.async.cg.shared.global [%0], [%1], 16;" :: "r"(dst), "l"(src))
#define CP_COMMIT() asm volatile("cp.async.commit_group;" ::: "memory")

__device__ __forceinline__ uint32_t smem_u32(const void* p) {
    uint32_t a;
    asm("{ .reg .u64 t; cvta.to.shared.u64 t, %1; cvt.u32.u64 %0, t; }" : "=r"(a) : "l"(p));
    return a;
}
__device__ __forceinline__ void mma_bf(float* c, const uint32_t* a, const uint32_t* b) {
    asm volatile("mma.sync.aligned.m16n8k16.row.col.f32.bf16.bf16.f32 "
        "{%0,%1,%2,%3}, {%4,%5,%6,%7}, {%8,%9}, {%0,%1,%2,%3};"
        : "+f"(c[0]), "+f"(c[1]), "+f"(c[2]), "+f"(c[3])
        : "r"(a[0]), "r"(a[1]), "r"(a[2]), "r"(a[3]), "r"(b[0]), "r"(b[1]));
}
__device__ __forceinline__ void mma_f16(float* c, const uint32_t* a, const uint32_t* b) {
    asm volatile("mma.sync.aligned.m16n8k16.row.col.f32.f16.f16.f32 "
        "{%0,%1,%2,%3}, {%4,%5,%6,%7}, {%8,%9}, {%0,%1,%2,%3};"
        : "+f"(c[0]), "+f"(c[1]), "+f"(c[2]), "+f"(c[3])
        : "r"(a[0]), "r"(a[1]), "r"(a[2]), "r"(a[3]), "r"(b[0]), "r"(b[1]));
}
__device__ __forceinline__ void ldsm_x4(uint32_t* r, uint32_t addr) {
    asm volatile("ldmatrix.sync.aligned.m8n8.x4.shared.b16 {%0,%1,%2,%3}, [%4];"
        : "=r"(r[0]), "=r"(r[1]), "=r"(r[2]), "=r"(r[3]) : "r"(addr));
}
// 64B rows, 4x16B blocks, XOR swizzle by row&3
__device__ __forceinline__ uint32_t sw_addr(uint32_t tile, int row, int cb) {
    return tile + (uint32_t)row * 64 + (uint32_t)((cb ^ (row & 3)) << 4);
}

// ================= conversions =================
__global__ void splitX(const float* __restrict__ src)
{
    int i = blockIdx.x * blockDim.x + threadIdx.x;
    float v = src[i];
    __nv_bfloat16 bh = __float2bfloat16(v);
    g_xbh[i] = bh;
    g_xbl[i] = __float2bfloat16(v - __bfloat162float(bh));
    __half fh = __float2half(v);
    g_xfh[i] = fh;
    g_xfl[i] = __float2half(v - __half2float(fh));
}
__global__ void splitWb(const float* __restrict__ Wq, const float* __restrict__ Wkv)
{
    int i = blockIdx.x * blockDim.x + threadIdx.x;
    float v = (i < DD) ? Wq[i] : Wkv[i - DD];
    __nv_bfloat16 h = __float2bfloat16(v);
    g_wbh[i] = h;
    g_wbl[i] = __float2bfloat16(v - __bfloat162float(h));
}
__global__ void convH(const float* __restrict__ Wkv, const float* __restrict__ Wout)
{
    int i = blockIdx.x * blockDim.x + threadIdx.x;
    if (i < DD) g_wv[i] = __float2half(Wkv[DD + i]);
    else        g_wo[i - DD] = __float2half(Wout[i - DD]);
}

// ================= tensor-core GEMM (R10: 128x128 tile, warp 32x64) ==========
// 8 warps 4x2, K-chunk 32, 3-stage pipeline, XOR-swizzled 64B rows,
// one __syncthreads per chunk, 2 CTAs/SM.
// MODE 0: QK bf16 3-pass (N=2048), MODE 1: V fp16 2-pass, MODE 2: OUT fp16 2-pass.
#define TILEB 8192                   // 128 rows x 64B
#define NCHUNK 32
#define NSTAGE 3

template<int MODE>
__global__ void __launch_bounds__(256, 2) gemm_tc(
    const float* __restrict__ bias0, const float* __restrict__ bias1, float* __restrict__ out)
{
    constexpr int NT = (MODE == 0) ? 4 : 3;
    constexpr int STAGE = NT * TILEB;
    extern __shared__ char smem[];
    uint32_t sb = smem_u32(smem);
    const int t = threadIdx.x;
    const int wid = t >> 5;
    const int lane = t & 31;
    const int g  = lane >> 2;
    const int tg = lane & 3;
    const int wm = wid >> 1;
    const int wn = wid & 1;
    const int m0 = blockIdx.y * 128;
    const int n0 = blockIdx.x * 128;

    const char *A0, *A1, *B0, *B1 = nullptr;
    if (MODE == 0) { A0 = (const char*)g_xbh; A1 = (const char*)g_xbl;
                     B0 = (const char*)g_wbh; B1 = (const char*)g_wbl; }
    else if (MODE == 1) { A0 = (const char*)g_xfh; A1 = (const char*)g_xfl;
                          B0 = (const char*)g_wv; }
    else { A0 = (const char*)g_cmh; A1 = (const char*)g_cml;
           B0 = (const char*)g_wo; }

    const int arow = lane & 15;
    const int acb  = (lane >> 4) & 1;
    const int brow = (lane & 7) + ((lane >> 4) & 1) * 8;
    const int bcb  = (lane >> 3) & 1;

    float c[2][8][4];
    #pragma unroll
    for (int i = 0; i < 2; i++)
        #pragma unroll
        for (int j = 0; j < 8; j++)
            #pragma unroll
            for (int q = 0; q < 4; q++) c[i][j][q] = 0.f;

    auto load_chunk = [&](uint32_t stage, int kc) {
        int kb = kc * 64;
        #pragma unroll
        for (int r = 0; r < 2; r++) {
            int j   = t + r * 256;
            int row = j >> 2;
            int cb  = j & 3;
            uint32_t d = (uint32_t)row * 64 + (uint32_t)((cb ^ (row & 3)) << 4);
            int off = kb + cb * 16;
            CP_ASYNC16(stage + 0*TILEB + d, A0 + (size_t)(m0 + row) * 2048 + off);
            CP_ASYNC16(stage + 1*TILEB + d, A1 + (size_t)(m0 + row) * 2048 + off);
            CP_ASYNC16(stage + 2*TILEB + d, B0 + (size_t)(n0 + row) * 2048 + off);
            if (NT == 4)
                CP_ASYNC16(stage + 3*TILEB + d, B1 + (size_t)(n0 + row) * 2048 + off);
        }
    };

    load_chunk(sb, 0);               CP_COMMIT();
    load_chunk(sb + STAGE, 1);       CP_COMMIT();

    int stg = 0;
    for (int kc = 0; kc < NCHUNK; kc++) {
        if (kc < NCHUNK - 1) asm volatile("cp.async.wait_group 1;" ::: "memory");
        else                 asm volatile("cp.async.wait_group 0;" ::: "memory");
        __syncthreads();

        uint32_t Ah = sb + stg * STAGE + 0*TILEB;
        uint32_t Al = sb + stg * STAGE + 1*TILEB;
        uint32_t Bh = sb + stg * STAGE + 2*TILEB;
        uint32_t Bl = Bh + TILEB;

        #pragma unroll
        for (int ks = 0; ks < 2; ks++) {
            uint32_t ah[2][4], al[2][4];
            #pragma unroll
            for (int i = 0; i < 2; i++) {
                int row = wm * 32 + i * 16 + arow;
                int cb  = ks * 2 + acb;
                ldsm_x4(ah[i], sw_addr(Ah, row, cb));
                ldsm_x4(al[i], sw_addr(Al, row, cb));
            }
            #pragma unroll
            for (int jj = 0; jj < 4; jj++) {
                int row = wn * 64 + jj * 16 + brow;
                int cb  = ks * 2 + bcb;
                if (MODE == 0) {
                    uint32_t bh[4], bl[4];
                    ldsm_x4(bh, sw_addr(Bh, row, cb));
                    ldsm_x4(bl, sw_addr(Bl, row, cb));
                    #pragma unroll
                    for (int i = 0; i < 2; i++) {
                        mma_bf(c[i][2*jj],   ah[i], bh);
                        mma_bf(c[i][2*jj],   ah[i], bl);
                        mma_bf(c[i][2*jj],   al[i], bh);
                        mma_bf(c[i][2*jj+1], ah[i], bh + 2);
                        mma_bf(c[i][2*jj+1], ah[i], bl + 2);
                        mma_bf(c[i][2*jj+1], al[i], bh + 2);
                    }
                } else {
                    uint32_t bq[4];
                    ldsm_x4(bq, sw_addr(Bh, row, cb));
                    #pragma unroll
                    for (int i = 0; i < 2; i++) {
                        mma_f16(c[i][2*jj],   ah[i], bq);
                        mma_f16(c[i][2*jj],   al[i], bq);
                        mma_f16(c[i][2*jj+1], ah[i], bq + 2);
                        mma_f16(c[i][2*jj+1], al[i], bq + 2);
                    }
                }
            }
        }
        if (kc + 2 < NCHUNK) {
            int nstg = stg + 2; if (nstg >= NSTAGE) nstg -= NSTAGE;
            load_chunk(sb + nstg * STAGE, kc + 2);
            CP_COMMIT();
        }
        stg = (stg + 1 == NSTAGE) ? 0 : stg + 1;
    }

    // epilogue
    #pragma unroll
    for (int i = 0; i < 2; i++) {
        #pragma unroll
        for (int j = 0; j < 8; j++) {
            #pragma unroll
            for (int half = 0; half < 2; half++) {
                int m = m0 + wm * 32 + i * 16 + g + half * 8;
                int n = n0 + wn * 64 + j * 8 + 2 * tg;
                float v0 = c[i][j][half*2 + 0];
                float v1 = c[i][j][half*2 + 1];
                if (MODE == 0) {
                    int b_ = m >> 11, l = m & (LSEQ - 1);
                    int nloc = n & 1023;
                    int h = nloc >> 6, dh = nloc & 63;
                    const float* bias = (n < DMODEL) ? (bias0 + n) : (bias1 + n - DMODEL);
                    float* dst = ((n < DMODEL) ? g_Q : g_K)
                               + (((size_t)(b_ * NHEAD + h)) * LSEQ + l) * DHEAD + dh;
                    *(float2*)dst = make_float2(v0 + bias[0], v1 + bias[1]);
                } else if (MODE == 1) {
                    int b_ = m >> 11, l = m & (LSEQ - 1);
                    int h = n >> 6, dh = n & 63;
                    const float* bias = bias1 + DMODEL + n;
                    float* dst = g_V + (((size_t)(b_ * NHEAD + h)) * LSEQ + l) * DHEAD + dh;
                    *(float2*)dst = make_float2(v0 + bias[0], v1 + bias[1]);
                } else {
                    int b_ = m / MODROWS;
                    int i_ = m - b_ * MODROWS;
                    int l  = g_rowlist[b_ * MODROWS + i_];
                    *(float2*)(out + ((size_t)(b_ * LSEQ + l)) * DMODEL + n) =
                        make_float2(v0 + bias0[n], v1 + bias0[n + 1]);
                }
            }
        }
    }
}

// ================= M scores (fp32, 2 queries per warp) =================
__global__ void score_m_kernel(const int* __restrict__ idxs)
{
    int warp = (blockIdx.x * blockDim.x + threadIdx.x) >> 5;
    int lane = threadIdx.x & 31;
    int bh = warp / (LSEQ/2);
    int l0 = (warp % (LSEQ/2)) * 2;
    const float* qr = g_Q + ((size_t)bh*LSEQ + l0) * DHEAD;
    float qa0 = qr[lane],         qa1 = qr[lane + 32];
    float qb0 = qr[DHEAD + lane], qb1 = qr[DHEAD + lane + 32];
    float mxa = -1e30f, sma = 0.f;
    float mxb = -1e30f, smb = 0.f;
    const float* Kb = g_K + (size_t)bh*LSEQ*DHEAD;
    #pragma unroll 4
    for (int u = 0; u < UTOP; u++) {
        int kia = idxs[l0*UTOP + u];
        int kib = idxs[(l0+1)*UTOP + u];
        const float* kra = Kb + (size_t)kia*DHEAD;
        const float* krb = Kb + (size_t)kib*DHEAD;
        float sa = qa0*kra[lane] + qa1*kra[lane + 32];
        float sb = qb0*krb[lane] + qb1*krb[lane + 32];
        #pragma unroll
        for (int o = 16; o; o >>= 1) {
            sa += __shfl_xor_sync(0xffffffffu, sa, o);
            sb += __shfl_xor_sync(0xffffffffu, sb, o);
        }
        mxa = fmaxf(mxa, sa); sma += sa;
        mxb = fmaxf(mxb, sb); smb += sb;
    }
    if (lane == 0) {
        g_M[(size_t)bh*LSEQ + l0]     = mxa - sma * (1.0f / UTOP);
        g_M[(size_t)bh*LSEQ + l0 + 1] = mxb - smb * (1.0f / UTOP);
    }
}

// ================= top-U =================
__global__ void topk_kernel()
{
    int bh = blockIdx.x;
    __shared__ float vals[LSEQ];
    __shared__ float wv[8];
    __shared__ int   wi[8];
    int t = threadIdx.x, lane = t & 31, wid = t >> 5;
    for (int i = t; i < LSEQ; i += 256) vals[i] = g_M[(size_t)bh*LSEQ + i];
    __syncthreads();
    for (int it = 0; it < UTOP; it++) {
        float v = -2e30f; int bi = 0;
        int base = t * 8;
        #pragma unroll
        for (int j = 0; j < 8; j++) {
            float x = vals[base + j];
            if (x > v) { v = x; bi = base + j; }
        }
        #pragma unroll
        for (int o = 16; o; o >>= 1) {
            float ov = __shfl_xor_sync(0xffffffffu, v, o);
            int   oi = __shfl_xor_sync(0xffffffffu, bi, o);
            if (ov > v) { v = ov; bi = oi; }
        }
        if (lane == 0) { wv[wid] = v; wi[wid] = bi; }
        __syncthreads();
        if (t < 32) {
            float v2 = (t < 8) ? wv[t] : -2e30f;
            int   i2 = (t < 8) ? wi[t] : 0;
            #pragma unroll
            for (int o = 4; o; o >>= 1) {
                float ov = __shfl_xor_sync(0xffffffffu, v2, o);
                int   oi = __shfl_xor_sync(0xffffffffu, i2, o);
                if (ov > v2) { v2 = ov; i2 = oi; }
            }
            if (t == 0) { g_top[bh*UTOP + it] = i2; vals[i2] = -1e30f; }
        }
        __syncthreads();
    }
}

// ================= V mean finish =================
__global__ void vmean_fin()
{
    int bh = blockIdx.x, dh = threadIdx.x;
    float s = 0.f;
    #pragma unroll
    for (int p = 0; p < KSPLIT; p++) s += g_vpart[((size_t)bh*KSPLIT + p)*DHEAD + dh];
    g_vmean[bh*DHEAD + dh] = s * (1.0f / LSEQ);
}

// ================= flash-split attention (+ V-mean partials) =================
__global__ void attn_flash()
{
    extern __shared__ float sm[];
    float* Qt   = sm;
    float* P    = sm + UTOP*DHEAD;
    float* mrow = P + UTOP*KS_KEYS;
    float* srow = mrow + UTOP;
    int ks = blockIdx.x, bh = blockIdx.y;
    int t = threadIdx.x, lane = t & 31, wid = t >> 5;

    for (int i = t; i < UTOP*DHEAD; i += 256) {
        int u = i >> 6, d = i & 63;
        Qt[i] = g_Q[((size_t)bh*LSEQ + g_top[bh*UTOP + u])*DHEAD + d];
    }
    __syncthreads();

    int k = ks * KS_KEYS + t;
    const float4* Kr = (const float4*)(g_K + ((size_t)bh*LSEQ + k)*DHEAD);
    float S[UTOP];
    #pragma unroll
    for (int u = 0; u < UTOP; u++) S[u] = 0.f;
    #pragma unroll
    for (int c = 0; c < 16; c++) {
        float4 kv = Kr[c];
        #pragma unroll
        for (int u = 0; u < UTOP; u++) {
            float4 qv = *(const float4*)(Qt + u*DHEAD + c*4);
            S[u] += kv.x*qv.x + kv.y*qv.y + kv.z*qv.z + kv.w*qv.w;
        }
    }
    #pragma unroll
    for (int u = 0; u < UTOP; u++) P[u*KS_KEYS + t] = S[u] * 0.125f;
    __syncthreads();

    for (int i = 0; i < 5; i++) {
        int u = wid + i*8;
        float* row = P + u*KS_KEYS;
        float m = -1e30f;
        #pragma unroll
        for (int j = 0; j < 8; j++) m = fmaxf(m, row[lane + 32*j]);
        #pragma unroll
        for (int o = 16; o; o >>= 1) m = fmaxf(m, __shfl_xor_sync(0xffffffffu, m, o));
        float s = 0.f;
        #pragma unroll
        for (int j = 0; j < 8; j++) {
            float e = __expf(row[lane + 32*j] - m);
            row[lane + 32*j] = e;
            s += e;
        }
        #pragma unroll
        for (int o = 16; o; o >>= 1) s += __shfl_xor_sync(0xffffffffu, s, o);
        if (lane == 0) { mrow[u] = m; srow[u] = s; }
    }
    __syncthreads();

    int d = t & 63, ug = t >> 6;
    float acc[10];
    #pragma unroll
    for (int i = 0; i < 10; i++) acc[i] = 0.f;
    float msum = 0.f;
    const float* Vb = g_V + ((size_t)bh*LSEQ + ks*KS_KEYS)*DHEAD + d;
    for (int kc = 0; kc < KS_KEYS/4; kc++) {
        float v0 = Vb[(size_t)(kc*4+0)*DHEAD];
        float v1 = Vb[(size_t)(kc*4+1)*DHEAD];
        float v2 = Vb[(size_t)(kc*4+2)*DHEAD];
        float v3 = Vb[(size_t)(kc*4+3)*DHEAD];
        msum += v0 + v1 + v2 + v3;
        #pragma unroll
        for (int i = 0; i < 10; i++) {
            int u = ug*10 + i;
            float4 p4 = *(const float4*)(P + u*KS_KEYS + kc*4);
            acc[i] += p4.x*v0 + p4.y*v1 + p4.z*v2 + p4.w*v3;
        }
    }
    if (ug == 0)
        g_vpart[((size_t)bh*KSPLIT + ks)*DHEAD + d] = msum;
    #pragma unroll
    for (int i = 0; i < 10; i++) {
        int u = ug*10 + i;
        g_pa[(((size_t)(bh*UTOP + u))*KSPLIT + ks)*DHEAD + d] = acc[i];
    }
    if (t < UTOP) {
        g_pm[(bh*UTOP + t)*KSPLIT + ks] = mrow[t];
        g_ps[(bh*UTOP + t)*KSPLIT + ks] = srow[t];
    }
}

__global__ void attn_combine()
{
    int bhu = blockIdx.x;
    int d = threadIdx.x;
    float m = -1e30f;
    #pragma unroll
    for (int j = 0; j < KSPLIT; j++) m = fmaxf(m, g_pm[bhu*KSPLIT + j]);
    float s = 0.f, a = 0.f;
    #pragma unroll
    for (int j = 0; j < KSPLIT; j++) {
        float w = __expf(g_pm[bhu*KSPLIT + j] - m);
        s += w * g_ps[bhu*KSPLIT + j];
        a += w * g_pa[((size_t)bhu*KSPLIT + j)*DHEAD + d];
    }
    g_ctx[(size_t)bhu*DHEAD + d] = a / s;
}

// ================= output-projection compaction =================
__global__ void sel_clear()
{
    int i = blockIdx.x * blockDim.x + threadIdx.x;
    g_selu[i] = 0;
    if (i < BATCH*LSEQ) g_flags[i] = 0;
}
__global__ void sel_mark()
{
    int bh = blockIdx.x, u = threadIdx.x;
    int l = g_top[bh*UTOP + u];
    g_selu[bh*LSEQ + l] = (unsigned char)(u + 1);
    int b_ = bh / NHEAD;
    g_flags[b_*LSEQ + l] = 1;
}
__global__ void compact_kernel()
{
    int b = blockIdx.x, t = threadIdx.x;
    __shared__ int cnts[256];
    __shared__ int l0s;
    int mine[8];
    int cnt = 0;
    #pragma unroll
    for (int j = 0; j < 8; j++) {
        mine[j] = g_flags[b*LSEQ + t*8 + j];
        cnt += mine[j];
    }
    cnts[t] = cnt;
    __syncthreads();
    for (int off = 1; off < 256; off <<= 1) {
        int v = (t >= off) ? cnts[t - off] : 0;
        __syncthreads();
        cnts[t] += v;
        __syncthreads();
    }
    int pos = cnts[t] - cnt;
    int total = cnts[255];
    #pragma unroll
    for (int j = 0; j < 8; j++)
        if (mine[j]) g_rowlist[b*MODROWS + pos++] = t*8 + j;
    __syncthreads();
    if (t == 0) l0s = g_rowlist[b*MODROWS];
    __syncthreads();
    for (int i = total + t; i < MODROWS; i += 256) g_rowlist[b*MODROWS + i] = l0s;
}
__global__ void build_cmod()
{
    int idx = blockIdx.x * blockDim.x + threadIdx.x;
    int d = idx & 1023;
    int r = (idx >> 10) % MODROWS;
    int b = idx / (MODROWS * 1024);
    int l = g_rowlist[b*MODROWS + r];
    int h = d >> 6;
    int bh = b * NHEAD + h;
    unsigned char u = g_selu[bh*LSEQ + l];
    float v = u ? g_ctx[((size_t)bh*UTOP + (u-1))*DHEAD + (d & 63)]
                : g_vmean[bh*DHEAD + (d & 63)];
    __half hi = __float2half(v);
    g_cmh[idx] = hi;
    g_cml[idx] = __float2half(v - __half2float(hi));
}
__global__ void base_out_kernel(const float* __restrict__ Wout, const float* __restrict__ bout)
{
    int gid = blockIdx.x * 8 + (threadIdx.x >> 5);
    int lane = threadIdx.x & 31;
    int b = gid >> 10, n = gid & 1023;
    const float* w = Wout + (size_t)n * DMODEL;
    const float* cb = g_vmean + b * DMODEL;
    float s = 0.f;
    #pragma unroll 8
    for (int k = lane; k < DMODEL; k += 32) s += cb[k] * w[k];
    #pragma unroll
    for (int o = 16; o; o >>= 1) s += __shfl_xor_sync(0xffffffffu, s, o);
    if (lane == 0) g_baseout[b*DMODEL + n] = s + bout[n];
}
__global__ void broadcast_base(float* __restrict__ out)
{
    int idx = blockIdx.x * blockDim.x + threadIdx.x;
    int e = idx * 4;
    int b = e >> 21;
    float4 v = *(const float4*)(g_baseout + b*DMODEL + (e & 1023));
    *(float4*)(out + e) = v;
}

// -----------------------------------------------------------------------------
extern "C" void kernel_launch(void* const* d_in, const int* in_sizes, int n_in,
                              void* d_out, int out_size)
{
    const float* x    = (const float*)d_in[0];
    const float* Wq   = (const float*)d_in[1];
    const float* bq   = (const float*)d_in[2];
    const float* Wkv  = (const float*)d_in[3];
    const float* bkv  = (const float*)d_in[4];
    const float* Wout = (const float*)d_in[5];
    const float* bout = (const float*)d_in[6];
    const int*   idxs = (const int*)d_in[7];
    float* out = (float*)d_out;

    cudaFuncSetAttribute(gemm_tc<0>, cudaFuncAttributeMaxDynamicSharedMemorySize, NSTAGE*4*TILEB);
    cudaFuncSetAttribute(gemm_tc<1>, cudaFuncAttributeMaxDynamicSharedMemorySize, NSTAGE*3*TILEB);
    cudaFuncSetAttribute(gemm_tc<2>, cudaFuncAttributeMaxDynamicSharedMemorySize, NSTAGE*3*TILEB);
    int attn_smem = (UTOP*DHEAD + UTOP*KS_KEYS + 2*UTOP) * sizeof(float);
    cudaFuncSetAttribute(attn_flash, cudaFuncAttributeMaxDynamicSharedMemorySize, attn_smem);

    // side stream + fork/join events (host-side objects; no device allocation)
    cudaStream_t s1;
    cudaStreamCreateWithFlags(&s1, cudaStreamNonBlocking);
    cudaEvent_t evConv, evQK, evV, evF2, evJ2;
    cudaEventCreateWithFlags(&evConv, cudaEventDisableTiming);
    cudaEventCreateWithFlags(&evQK,   cudaEventDisableTiming);
    cudaEventCreateWithFlags(&evV,    cudaEventDisableTiming);
    cudaEventCreateWithFlags(&evF2,   cudaEventDisableTiming);
    cudaEventCreateWithFlags(&evJ2,   cudaEventDisableTiming);

    // origin: x + QK-weight conversions
    splitX<<<MROWS*DMODEL/256, 256>>>(x);
    splitWb<<<2*DD/256, 256>>>(Wq, Wkv);
    // fork: convH (V/out weights, DRAM-bound) + sel_clear on s1, overlapping gemm_QK
    cudaEventRecord(evConv, 0);
    cudaStreamWaitEvent(s1, evConv, 0);
    convH<<<2*DD/256, 256, 0, s1>>>(Wkv, Wout);
    sel_clear<<<256, 256, 0, s1>>>();

    // origin: QK projection (tensor-bound)
    gemm_tc<0><<<dim3(2*DMODEL/128, MROWS/128), 256, NSTAGE*4*TILEB>>>(bq, bkv, nullptr);
    cudaEventRecord(evQK, 0);

    // s1: V projection AFTER gemm_QK -> runs concurrently with the score chain
    cudaStreamWaitEvent(s1, evQK, 0);
    gemm_tc<1><<<dim3(DMODEL/128, MROWS/128), 256, NSTAGE*3*TILEB, s1>>>(nullptr, bkv, nullptr);
    cudaEventRecord(evV, s1);

    // origin: selection chain (L2/issue-bound), concurrent with gemm_V
    score_m_kernel<<<BHL/16, 256>>>(idxs);
    topk_kernel<<<BATCH*NHEAD, 256>>>();
    sel_mark<<<BATCH*NHEAD, UTOP>>>();
    compact_kernel<<<BATCH, 256>>>();

    // join: attention needs V + selection
    cudaStreamWaitEvent(0, evV, 0);
    attn_flash<<<dim3(KSPLIT, BATCH*NHEAD), 256, attn_smem>>>();
    vmean_fin<<<BATCH*NHEAD, 64>>>();

    // fork 2: base rows + broadcast on s1; ctx combine + cmod on origin
    cudaEventRecord(evF2, 0);
    cudaStreamWaitEvent(s1, evF2, 0);
    base_out_kernel<<<BATCH*DMODEL/8, 256, 0, s1>>>(Wout, bout);
    broadcast_base<<<MROWS*DMODEL/1024, 256, 0, s1>>>(out);
    cudaEventRecord(evJ2, s1);

    attn_combine<<<BATCH*NHEAD*UTOP, 64>>>();
    build_cmod<<<BATCH*MODROWS*DMODEL/256, 256>>>();

    // join: scatter GEMM must follow the broadcast it overwrites
    cudaStreamWaitEvent(0, evJ2, 0);
    gemm_tc<2><<<dim3(8, BATCH*MODROWS/128), 256, NSTAGE*3*TILEB>>>(bout, nullptr, out);
}

// round 15
// speedup vs baseline: 1.2353x; 1.0343x over previous
#include <cuda_runtime.h>
#include <cuda_bf16.h>
#include <cuda_fp16.h>
#include <cstdint>
#include <math.h>

#define BATCH 2
#define LSEQ 2048
#define DMODEL 1024
#define NHEAD 16
#define DHEAD 64
#define UTOP 40
#define MROWS (BATCH*LSEQ)          // 4096
#define BHL (BATCH*NHEAD*LSEQ)      // 65536
#define KSPLIT 8
#define KS_KEYS (LSEQ/KSPLIT)       // 256
#define MODROWS 640
#define DD (DMODEL*DMODEL)

// ---------------- scratch ----------------
__device__ float g_Q[BATCH*NHEAD*LSEQ*DHEAD];
__device__ float g_K[BATCH*NHEAD*LSEQ*DHEAD];
__device__ float g_V[BATCH*NHEAD*LSEQ*DHEAD];
__device__ float g_M[BHL];
__device__ int   g_top[BATCH*NHEAD*UTOP];
__device__ float g_ctx[BATCH*NHEAD*UTOP*DHEAD];
__device__ float g_vpart[BATCH*NHEAD*KSPLIT*DHEAD];
__device__ float g_vmean[BATCH*NHEAD*DHEAD];
__device__ __nv_bfloat16 g_xbh[MROWS*DMODEL], g_xbl[MROWS*DMODEL];
__device__ __half        g_xfh[MROWS*DMODEL], g_xfl[MROWS*DMODEL];
__device__ __nv_bfloat16 g_wbh[2*DD], g_wbl[2*DD];   // [Wq ; Wkv_K] bf16 hi/lo
__device__ __half        g_wv[DD];                   // Wkv_V fp16
__device__ __half        g_wo[DD];                   // Wout fp16
__device__ __half        g_cmh[BATCH*MODROWS*DMODEL], g_cml[BATCH*MODROWS*DMODEL];
__device__ float g_pm[BATCH*NHEAD*UTOP*KSPLIT];
__device__ float g_ps[BATCH*NHEAD*UTOP*KSPLIT];
__device__ float g_pa[BATCH*NHEAD*UTOP*KSPLIT*DHEAD];
__device__ unsigned char g_selu[BATCH*NHEAD*LSEQ];
__device__ int   g_flags[BATCH*LSEQ];
__device__ int   g_rowlist[BATCH*MODROWS];
__device__ float g_baseout[BATCH*DMODEL];

// ================= helpers =================
#define CP_ASYNC16(dst, src) \
    asm volatile("cp.async.cg.shared.global [%0], [%1], 16;" :: "r"(dst), "l"(src))
#define CP_COMMIT() asm volatile("cp.async.commit_group;" ::: "memory")

__device__ __forceinline__ uint32_t smem_u32(const void* p) {
    uint32_t a;
    asm("{ .reg .u64 t; cvta.to.shared.u64 t, %1; cvt.u32.u64 %0, t; }" : "=r"(a) : "l"(p));
    return a;
}
__device__ __forceinline__ void mma_bf(float* c, const uint32_t* a, const uint32_t* b) {
    asm volatile("mma.sync.aligned.m16n8k16.row.col.f32.bf16.bf16.f32 "
        "{%0,%1,%2,%3}, {%4,%5,%6,%7}, {%8,%9}, {%0,%1,%2,%3};"
        : "+f"(c[0]), "+f"(c[1]), "+f"(c[2]), "+f"(c[3])
        : "r"(a[0]), "r"(a[1]), "r"(a[2]), "r"(a[3]), "r"(b[0]), "r"(b[1]));
}
__device__ __forceinline__ void mma_f16(float* c, const uint32_t* a, const uint32_t* b) {
    asm volatile("mma.sync.aligned.m16n8k16.row.col.f32.f16.f16.f32 "
        "{%0,%1,%2,%3}, {%4,%5,%6,%7}, {%8,%9}, {%0,%1,%2,%3};"
        : "+f"(c[0]), "+f"(c[1]), "+f"(c[2]), "+f"(c[3])
        : "r"(a[0]), "r"(a[1]), "r"(a[2]), "r"(a[3]), "r"(b[0]), "r"(b[1]));
}
__device__ __forceinline__ void ldsm_x4(uint32_t* r, uint32_t addr) {
    asm volatile("ldmatrix.sync.aligned.m8n8.x4.shared.b16 {%0,%1,%2,%3}, [%4];"
        : "=r"(r[0]), "=r"(r[1]), "=r"(r[2]), "=r"(r[3]) : "r"(addr));
}
// 64B rows, 4x16B blocks, XOR swizzle by row&3
__device__ __forceinline__ uint32_t sw_addr(uint32_t tile, int row, int cb) {
    return tile + (uint32_t)row * 64 + (uint32_t)((cb ^ (row & 3)) << 4);
}

// ================= conversions (float4 vectorized) =================
__global__ void splitX(const float* __restrict__ src)
{
    int i = (blockIdx.x * blockDim.x + threadIdx.x) * 4;
    float4 v = *(const float4*)(src + i);
    __nv_bfloat162 bh0, bh1, bl0, bl1;
    __half2 fh0, fh1, fl0, fl1;
    float a[4] = {v.x, v.y, v.z, v.w};
    __nv_bfloat16 b16[4]; __nv_bfloat16 b16l[4];
    __half h16[4]; __half h16l[4];
    #pragma unroll
    for (int j = 0; j < 4; j++) {
        b16[j] = __float2bfloat16(a[j]);
        b16l[j] = __float2bfloat16(a[j] - __bfloat162float(b16[j]));
        h16[j] = __float2half(a[j]);
        h16l[j] = __float2half(a[j] - __half2float(h16[j]));
    }
    bh0.x = b16[0]; bh0.y = b16[1]; bh1.x = b16[2]; bh1.y = b16[3];
    bl0.x = b16l[0]; bl0.y = b16l[1]; bl1.x = b16l[2]; bl1.y = b16l[3];
    fh0.x = h16[0]; fh0.y = h16[1]; fh1.x = h16[2]; fh1.y = h16[3];
    fl0.x = h16l[0]; fl0.y = h16l[1]; fl1.x = h16l[2]; fl1.y = h16l[3];
    *(__nv_bfloat162*)(g_xbh + i) = bh0; *(__nv_bfloat162*)(g_xbh + i + 2) = bh1;
    *(__nv_bfloat162*)(g_xbl + i) = bl0; *(__nv_bfloat162*)(g_xbl + i + 2) = bl1;
    *(__half2*)(g_xfh + i) = fh0; *(__half2*)(g_xfh + i + 2) = fh1;
    *(__half2*)(g_xfl + i) = fl0; *(__half2*)(g_xfl + i + 2) = fl1;
}
__global__ void splitWb(const float* __restrict__ Wq, const float* __restrict__ Wkv)
{
    int i = (blockIdx.x * blockDim.x + threadIdx.x) * 4;
    float4 v = (i < DD) ? *(const float4*)(Wq + i) : *(const float4*)(Wkv + i - DD);
    float a[4] = {v.x, v.y, v.z, v.w};
    __nv_bfloat16 h[4], l[4];
    #pragma unroll
    for (int j = 0; j < 4; j++) {
        h[j] = __float2bfloat16(a[j]);
        l[j] = __float2bfloat16(a[j] - __bfloat162float(h[j]));
    }
    __nv_bfloat162 h0, h1, l0, l1;
    h0.x = h[0]; h0.y = h[1]; h1.x = h[2]; h1.y = h[3];
    l0.x = l[0]; l0.y = l[1]; l1.x = l[2]; l1.y = l[3];
    *(__nv_bfloat162*)(g_wbh + i) = h0; *(__nv_bfloat162*)(g_wbh + i + 2) = h1;
    *(__nv_bfloat162*)(g_wbl + i) = l0; *(__nv_bfloat162*)(g_wbl + i + 2) = l1;
}
__global__ void convH(const float* __restrict__ Wkv, const float* __restrict__ Wout)
{
    int i = (blockIdx.x * blockDim.x + threadIdx.x) * 4;
    float4 v = (i < DD) ? *(const float4*)(Wkv + DD + i) : *(const float4*)(Wout + i - DD);
    __half2 h0, h1;
    h0.x = __float2half(v.x); h0.y = __float2half(v.y);
    h1.x = __float2half(v.z); h1.y = __float2half(v.w);
    __half* dst = (i < DD) ? (g_wv + i) : (g_wo + i - DD);
    *(__half2*)dst = h0; *(__half2*)(dst + 2) = h1;
}

// ================= tensor-core GEMM (R10: 128x128 tile, warp 32x64) ==========
#define TILEB 8192                   // 128 rows x 64B
#define NCHUNK 32
#define NSTAGE 3

template<int MODE>
__global__ void __launch_bounds__(256, 2) gemm_tc(
    const float* __restrict__ bias0, const float* __restrict__ bias1, float* __restrict__ out)
{
    constexpr int NT = (MODE == 0) ? 4 : 3;
    constexpr int STAGE = NT * TILEB;
    extern __shared__ char smem[];
    uint32_t sb = smem_u32(smem);
    const int t = threadIdx.x;
    const int wid = t >> 5;
    const int lane = t & 31;
    const int g  = lane >> 2;
    const int tg = lane & 3;
    const int wm = wid >> 1;
    const int wn = wid & 1;
    const int m0 = blockIdx.y * 128;
    const int n0 = blockIdx.x * 128;

    const char *A0, *A1, *B0, *B1 = nullptr;
    if (MODE == 0) { A0 = (const char*)g_xbh; A1 = (const char*)g_xbl;
                     B0 = (const char*)g_wbh; B1 = (const char*)g_wbl; }
    else if (MODE == 1) { A0 = (const char*)g_xfh; A1 = (const char*)g_xfl;
                          B0 = (const char*)g_wv; }
    else { A0 = (const char*)g_cmh; A1 = (const char*)g_cml;
           B0 = (const char*)g_wo; }

    const int arow = lane & 15;
    const int acb  = (lane >> 4) & 1;
    const int brow = (lane & 7) + ((lane >> 4) & 1) * 8;
    const int bcb  = (lane >> 3) & 1;

    float c[2][8][4];
    #pragma unroll
    for (int i = 0; i < 2; i++)
        #pragma unroll
        for (int j = 0; j < 8; j++)
            #pragma unroll
            for (int q = 0; q < 4; q++) c[i][j][q] = 0.f;

    auto load_chunk = [&](uint32_t stage, int kc) {
        int kb = kc * 64;
        #pragma unroll
        for (int r = 0; r < 2; r++) {
            int j   = t + r * 256;
            int row = j >> 2;
            int cb  = j & 3;
            uint32_t d = (uint32_t)row * 64 + (uint32_t)((cb ^ (row & 3)) << 4);
            int off = kb + cb * 16;
            CP_ASYNC16(stage + 0*TILEB + d, A0 + (size_t)(m0 + row) * 2048 + off);
            CP_ASYNC16(stage + 1*TILEB + d, A1 + (size_t)(m0 + row) * 2048 + off);
            CP_ASYNC16(stage + 2*TILEB + d, B0 + (size_t)(n0 + row) * 2048 + off);
            if (NT == 4)
                CP_ASYNC16(stage + 3*TILEB + d, B1 + (size_t)(n0 + row) * 2048 + off);
        }
    };

    load_chunk(sb, 0);               CP_COMMIT();
    load_chunk(sb + STAGE, 1);       CP_COMMIT();

    int stg = 0;
    for (int kc = 0; kc < NCHUNK; kc++) {
        if (kc < NCHUNK - 1) asm volatile("cp.async.wait_group 1;" ::: "memory");
        else                 asm volatile("cp.async.wait_group 0;" ::: "memory");
        __syncthreads();

        uint32_t Ah = sb + stg * STAGE + 0*TILEB;
        uint32_t Al = sb + stg * STAGE + 1*TILEB;
        uint32_t Bh = sb + stg * STAGE + 2*TILEB;
        uint32_t Bl = Bh + TILEB;

        #pragma unroll
        for (int ks = 0; ks < 2; ks++) {
            uint32_t ah[2][4], al[2][4];
            #pragma unroll
            for (int i = 0; i < 2; i++) {
                int row = wm * 32 + i * 16 + arow;
                int cb  = ks * 2 + acb;
                ldsm_x4(ah[i], sw_addr(Ah, row, cb));
                ldsm_x4(al[i], sw_addr(Al, row, cb));
            }
            #pragma unroll
            for (int jj = 0; jj < 4; jj++) {
                int row = wn * 64 + jj * 16 + brow;
                int cb  = ks * 2 + bcb;
                if (MODE == 0) {
                    uint32_t bh[4], bl[4];
                    ldsm_x4(bh, sw_addr(Bh, row, cb));
                    ldsm_x4(bl, sw_addr(Bl, row, cb));
                    #pragma unroll
                    for (int i = 0; i < 2; i++) {
                        mma_bf(c[i][2*jj],   ah[i], bh);
                        mma_bf(c[i][2*jj],   ah[i], bl);
                        mma_bf(c[i][2*jj],   al[i], bh);
                        mma_bf(c[i][2*jj+1], ah[i], bh + 2);
                        mma_bf(c[i][2*jj+1], ah[i], bl + 2);
                        mma_bf(c[i][2*jj+1], al[i], bh + 2);
                    }
                } else {
                    uint32_t bq[4];
                    ldsm_x4(bq, sw_addr(Bh, row, cb));
                    #pragma unroll
                    for (int i = 0; i < 2; i++) {
                        mma_f16(c[i][2*jj],   ah[i], bq);
                        mma_f16(c[i][2*jj],   al[i], bq);
                        mma_f16(c[i][2*jj+1], ah[i], bq + 2);
                        mma_f16(c[i][2*jj+1], al[i], bq + 2);
                    }
                }
            }
        }
        if (kc + 2 < NCHUNK) {
            int nstg = stg + 2; if (nstg >= NSTAGE) nstg -= NSTAGE;
            load_chunk(sb + nstg * STAGE, kc + 2);
            CP_COMMIT();
        }
        stg = (stg + 1 == NSTAGE) ? 0 : stg + 1;
    }

    // epilogue
    #pragma unroll
    for (int i = 0; i < 2; i++) {
        #pragma unroll
        for (int j = 0; j < 8; j++) {
            #pragma unroll
            for (int half = 0; half < 2; half++) {
                int m = m0 + wm * 32 + i * 16 + g + half * 8;
                int n = n0 + wn * 64 + j * 8 + 2 * tg;
                float v0 = c[i][j][half*2 + 0];
                float v1 = c[i][j][half*2 + 1];
                if (MODE == 0) {
                    int b_ = m >> 11, l = m & (LSEQ - 1);
                    int nloc = n & 1023;
                    int h = nloc >> 6, dh = nloc & 63;
                    const float* bias = (n < DMODEL) ? (bias0 + n) : (bias1 + n - DMODEL);
                    float* dst = ((n < DMODEL) ? g_Q : g_K)
                               + (((size_t)(b_ * NHEAD + h)) * LSEQ + l) * DHEAD + dh;
                    *(float2*)dst = make_float2(v0 + bias[0], v1 + bias[1]);
                } else if (MODE == 1) {
                    int b_ = m >> 11, l = m & (LSEQ - 1);
                    int h = n >> 6, dh = n & 63;
                    const float* bias = bias1 + DMODEL + n;
                    float* dst = g_V + (((size_t)(b_ * NHEAD + h)) * LSEQ + l) * DHEAD + dh;
                    *(float2*)dst = make_float2(v0 + bias[0], v1 + bias[1]);
                } else {
                    int b_ = m / MODROWS;
                    int i_ = m - b_ * MODROWS;
                    int l  = g_rowlist[b_ * MODROWS + i_];
                    *(float2*)(out + ((size_t)(b_ * LSEQ + l)) * DMODEL + n) =
                        make_float2(v0 + bias0[n], v1 + bias0[n + 1]);
                }
            }
        }
    }
}

// ================= M scores (fp32, 2 queries per warp) =================
__global__ void score_m_kernel(const int* __restrict__ idxs)
{
    int warp = (blockIdx.x * blockDim.x + threadIdx.x) >> 5;
    int lane = threadIdx.x & 31;
    int bh = warp / (LSEQ/2);
    int l0 = (warp % (LSEQ/2)) * 2;
    const float* qr = g_Q + ((size_t)bh*LSEQ + l0) * DHEAD;
    float qa0 = qr[lane],         qa1 = qr[lane + 32];
    float qb0 = qr[DHEAD + lane], qb1 = qr[DHEAD + lane + 32];
    float mxa = -1e30f, sma = 0.f;
    float mxb = -1e30f, smb = 0.f;
    const float* Kb = g_K + (size_t)bh*LSEQ*DHEAD;
    #pragma unroll 4
    for (int u = 0; u < UTOP; u++) {
        int kia = idxs[l0*UTOP + u];
        int kib = idxs[(l0+1)*UTOP + u];
        const float* kra = Kb + (size_t)kia*DHEAD;
        const float* krb = Kb + (size_t)kib*DHEAD;
        float sa = qa0*kra[lane] + qa1*kra[lane + 32];
        float sb = qb0*krb[lane] + qb1*krb[lane + 32];
        #pragma unroll
        for (int o = 16; o; o >>= 1) {
            sa += __shfl_xor_sync(0xffffffffu, sa, o);
            sb += __shfl_xor_sync(0xffffffffu, sb, o);
        }
        mxa = fmaxf(mxa, sa); sma += sa;
        mxb = fmaxf(mxb, sb); smb += sb;
    }
    if (lane == 0) {
        g_M[(size_t)bh*LSEQ + l0]     = mxa - sma * (1.0f / UTOP);
        g_M[(size_t)bh*LSEQ + l0 + 1] = mxb - smb * (1.0f / UTOP);
    }
}

// ================= top-U (fused sel_mark) =================
__global__ void topk_kernel()
{
    int bh = blockIdx.x;
    __shared__ float vals[LSEQ];
    __shared__ float wv[8];
    __shared__ int   wi[8];
    int t = threadIdx.x, lane = t & 31, wid = t >> 5;
    int b_ = bh / NHEAD;
    for (int i = t; i < LSEQ; i += 256) vals[i] = g_M[(size_t)bh*LSEQ + i];
    __syncthreads();
    for (int it = 0; it < UTOP; it++) {
        float v = -2e30f; int bi = 0;
        int base = t * 8;
        #pragma unroll
        for (int j = 0; j < 8; j++) {
            float x = vals[base + j];
            if (x > v) { v = x; bi = base + j; }
        }
        #pragma unroll
        for (int o = 16; o; o >>= 1) {
            float ov = __shfl_xor_sync(0xffffffffu, v, o);
            int   oi = __shfl_xor_sync(0xffffffffu, bi, o);
            if (ov > v) { v = ov; bi = oi; }
        }
        if (lane == 0) { wv[wid] = v; wi[wid] = bi; }
        __syncthreads();
        if (t < 32) {
            float v2 = (t < 8) ? wv[t] : -2e30f;
            int   i2 = (t < 8) ? wi[t] : 0;
            #pragma unroll
            for (int o = 4; o; o >>= 1) {
                float ov = __shfl_xor_sync(0xffffffffu, v2, o);
                int   oi = __shfl_xor_sync(0xffffffffu, i2, o);
                if (ov > v2) { v2 = ov; i2 = oi; }
            }
            if (t == 0) {
                g_top[bh*UTOP + it] = i2;
                g_selu[bh*LSEQ + i2] = (unsigned char)(it + 1);
                g_flags[b_*LSEQ + i2] = 1;
                vals[i2] = -1e30f;
            }
        }
        __syncthreads();
    }
}

// ================= V mean (standalone, on side stream) =================
__global__ void vmean_part()      // grid (KSPLIT, BH), block 64
{
    int p = blockIdx.x, bh = blockIdx.y, dh = threadIdx.x;
    float s = 0.f;
    const float* base = g_V + ((size_t)bh*LSEQ + p*KS_KEYS)*DHEAD + dh;
    #pragma unroll 4
    for (int j = 0; j < KS_KEYS; j++) s += base[(size_t)j*DHEAD];
    g_vpart[((size_t)bh*KSPLIT + p)*DHEAD + dh] = s;
}
__global__ void vmean_fin()
{
    int bh = blockIdx.x, dh = threadIdx.x;
    float s = 0.f;
    #pragma unroll
    for (int p = 0; p < KSPLIT; p++) s += g_vpart[((size_t)bh*KSPLIT + p)*DHEAD + dh];
    g_vmean[bh*DHEAD + dh] = s * (1.0f / LSEQ);
}

// ================= flash-split attention =================
__global__ void attn_flash()
{
    extern __shared__ float sm[];
    float* Qt   = sm;
    float* P    = sm + UTOP*DHEAD;
    float* mrow = P + UTOP*KS_KEYS;
    float* srow = mrow + UTOP;
    int ks = blockIdx.x, bh = blockIdx.y;
    int t = threadIdx.x, lane = t & 31, wid = t >> 5;

    for (int i = t; i < UTOP*DHEAD; i += 256) {
        int u = i >> 6, d = i & 63;
        Qt[i] = g_Q[((size_t)bh*LSEQ + g_top[bh*UTOP + u])*DHEAD + d];
    }
    __syncthreads();

    int k = ks * KS_KEYS + t;
    const float4* Kr = (const float4*)(g_K + ((size_t)bh*LSEQ + k)*DHEAD);
    float S[UTOP];
    #pragma unroll
    for (int u = 0; u < UTOP; u++) S[u] = 0.f;
    #pragma unroll
    for (int c = 0; c < 16; c++) {
        float4 kv = Kr[c];
        #pragma unroll
        for (int u = 0; u < UTOP; u++) {
            float4 qv = *(const float4*)(Qt + u*DHEAD + c*4);
            S[u] += kv.x*qv.x + kv.y*qv.y + kv.z*qv.z + kv.w*qv.w;
        }
    }
    #pragma unroll
    for (int u = 0; u < UTOP; u++) P[u*KS_KEYS + t] = S[u] * 0.125f;
    __syncthreads();

    for (int i = 0; i < 5; i++) {
        int u = wid + i*8;
        float* row = P + u*KS_KEYS;
        float m = -1e30f;
        #pragma unroll
        for (int j = 0; j < 8; j++) m = fmaxf(m, row[lane + 32*j]);
        #pragma unroll
        for (int o = 16; o; o >>= 1) m = fmaxf(m, __shfl_xor_sync(0xffffffffu, m, o));
        float s = 0.f;
        #pragma unroll
        for (int j = 0; j < 8; j++) {
            float e = __expf(row[lane + 32*j] - m);
            row[lane + 32*j] = e;
            s += e;
        }
        #pragma unroll
        for (int o = 16; o; o >>= 1) s += __shfl_xor_sync(0xffffffffu, s, o);
        if (lane == 0) { mrow[u] = m; srow[u] = s; }
    }
    __syncthreads();

    int d = t & 63, ug = t >> 6;
    float acc[10];
    #pragma unroll
    for (int i = 0; i < 10; i++) acc[i] = 0.f;
    const float* Vb = g_V + ((size_t)bh*LSEQ + ks*KS_KEYS)*DHEAD + d;
    for (int kc = 0; kc < KS_KEYS/4; kc++) {
        float v0 = Vb[(size_t)(kc*4+0)*DHEAD];
        float v1 = Vb[(size_t)(kc*4+1)*DHEAD];
        float v2 = Vb[(size_t)(kc*4+2)*DHEAD];
        float v3 = Vb[(size_t)(kc*4+3)*DHEAD];
        #pragma unroll
        for (int i = 0; i < 10; i++) {
            int u = ug*10 + i;
            float4 p4 = *(const float4*)(P + u*KS_KEYS + kc*4);
            acc[i] += p4.x*v0 + p4.y*v1 + p4.z*v2 + p4.w*v3;
        }
    }
    #pragma unroll
    for (int i = 0; i < 10; i++) {
        int u = ug*10 + i;
        g_pa[(((size_t)(bh*UTOP + u))*KSPLIT + ks)*DHEAD + d] = acc[i];
    }
    if (t < UTOP) {
        g_pm[(bh*UTOP + t)*KSPLIT + ks] = mrow[t];
        g_ps[(bh*UTOP + t)*KSPLIT + ks] = srow[t];
    }
}

__global__ void attn_combine()
{
    int bhu = blockIdx.x;
    int d = threadIdx.x;
    float m = -1e30f;
    #pragma unroll
    for (int j = 0; j < KSPLIT; j++) m = fmaxf(m, g_pm[bhu*KSPLIT + j]);
    float s = 0.f, a = 0.f;
    #pragma unroll
    for (int j = 0; j < KSPLIT; j++) {
        float w = __expf(g_pm[bhu*KSPLIT + j] - m);
        s += w * g_ps[bhu*KSPLIT + j];
        a += w * g_pa[((size_t)bhu*KSPLIT + j)*DHEAD + d];
    }
    g_ctx[(size_t)bhu*DHEAD + d] = a / s;
}

// ================= output-projection compaction =================
__global__ void sel_clear()
{
    int i = blockIdx.x * blockDim.x + threadIdx.x;
    g_selu[i] = 0;
    if (i < BATCH*LSEQ) g_flags[i] = 0;
}
__global__ void compact_kernel()
{
    int b = blockIdx.x, t = threadIdx.x;
    __shared__ int cnts[256];
    __shared__ int l0s;
    int mine[8];
    int cnt = 0;
    #pragma unroll
    for (int j = 0; j < 8; j++) {
        mine[j] = g_flags[b*LSEQ + t*8 + j];
        cnt += mine[j];
    }
    cnts[t] = cnt;
    __syncthreads();
    for (int off = 1; off < 256; off <<= 1) {
        int v = (t >= off) ? cnts[t - off] : 0;
        __syncthreads();
        cnts[t] += v;
        __syncthreads();
    }
    int pos = cnts[t] - cnt;
    int total = cnts[255];
    #pragma unroll
    for (int j = 0; j < 8; j++)
        if (mine[j]) g_rowlist[b*MODROWS + pos++] = t*8 + j;
    __syncthreads();
    if (t == 0) l0s = g_rowlist[b*MODROWS];
    __syncthreads();
    for (int i = total + t; i < MODROWS; i += 256) g_rowlist[b*MODROWS + i] = l0s;
}
__global__ void build_cmod()
{
    int idx = blockIdx.x * blockDim.x + threadIdx.x;
    int d = idx & 1023;
    int r = (idx >> 10) % MODROWS;
    int b = idx / (MODROWS * 1024);
    int l = g_rowlist[b*MODROWS + r];
    int h = d >> 6;
    int bh = b * NHEAD + h;
    unsigned char u = g_selu[bh*LSEQ + l];
    float v = u ? g_ctx[((size_t)bh*UTOP + (u-1))*DHEAD + (d & 63)]
                : g_vmean[bh*DHEAD + (d & 63)];
    __half hi = __float2half(v);
    g_cmh[idx] = hi;
    g_cml[idx] = __float2half(v - __half2float(hi));
}
__global__ void base_out_kernel(const float* __restrict__ Wout, const float* __restrict__ bout)
{
    int gid = blockIdx.x * 8 + (threadIdx.x >> 5);
    int lane = threadIdx.x & 31;
    int b = gid >> 10, n = gid & 1023;
    const float* w = Wout + (size_t)n * DMODEL;
    const float* cb = g_vmean + b * DMODEL;
    float s = 0.f;
    #pragma unroll 8
    for (int k = lane; k < DMODEL; k += 32) s += cb[k] * w[k];
    #pragma unroll
    for (int o = 16; o; o >>= 1) s += __shfl_xor_sync(0xffffffffu, s, o);
    if (lane == 0) g_baseout[b*DMODEL + n] = s + bout[n];
}
__global__ void broadcast_base(float* __restrict__ out)
{
    int idx = blockIdx.x * blockDim.x + threadIdx.x;
    int e = idx * 4;
    int b = e >> 21;
    float4 v = *(const float4*)(g_baseout + b*DMODEL + (e & 1023));
    *(float4*)(out + e) = v;
}

// -----------------------------------------------------------------------------
extern "C" void kernel_launch(void* const* d_in, const int* in_sizes, int n_in,
                              void* d_out, int out_size)
{
    const float* x    = (const float*)d_in[0];
    const float* Wq   = (const float*)d_in[1];
    const float* bq   = (const float*)d_in[2];
    const float* Wkv  = (const float*)d_in[3];
    const float* bkv  = (const float*)d_in[4];
    const float* Wout = (const float*)d_in[5];
    const float* bout = (const float*)d_in[6];
    const int*   idxs = (const int*)d_in[7];
    float* out = (float*)d_out;

    cudaFuncSetAttribute(gemm_tc<0>, cudaFuncAttributeMaxDynamicSharedMemorySize, NSTAGE*4*TILEB);
    cudaFuncSetAttribute(gemm_tc<1>, cudaFuncAttributeMaxDynamicSharedMemorySize, NSTAGE*3*TILEB);
    cudaFuncSetAttribute(gemm_tc<2>, cudaFuncAttributeMaxDynamicSharedMemorySize, NSTAGE*3*TILEB);
    int attn_smem = (UTOP*DHEAD + UTOP*KS_KEYS + 2*UTOP) * sizeof(float);
    cudaFuncSetAttribute(attn_flash, cudaFuncAttributeMaxDynamicSharedMemorySize, attn_smem);

    // side stream + events (host-side objects; no device allocation)
    cudaStream_t s1;
    cudaStreamCreateWithFlags(&s1, cudaStreamNonBlocking);
    cudaEvent_t evConv, evClr, evQK, evV, evS1;
    cudaEventCreateWithFlags(&evConv, cudaEventDisableTiming);
    cudaEventCreateWithFlags(&evClr,  cudaEventDisableTiming);
    cudaEventCreateWithFlags(&evQK,   cudaEventDisableTiming);
    cudaEventCreateWithFlags(&evV,    cudaEventDisableTiming);
    cudaEventCreateWithFlags(&evS1,   cudaEventDisableTiming);

    // origin: x + QK-weight conversions
    splitX<<<MROWS*DMODEL/1024, 256>>>(x);
    splitWb<<<2*DD/1024, 256>>>(Wq, Wkv);
    // fork: convH + sel_clear on s1, overlapping gemm_QK
    cudaEventRecord(evConv, 0);
    cudaStreamWaitEvent(s1, evConv, 0);
    convH<<<2*DD/1024, 256, 0, s1>>>(Wkv, Wout);
    sel_clear<<<256, 256, 0, s1>>>();
    cudaEventRecord(evClr, s1);

    // origin: QK projection (tensor-bound)
    gemm_tc<0><<<dim3(2*DMODEL/128, MROWS/128), 256, NSTAGE*4*TILEB>>>(bq, bkv, nullptr);
    cudaEventRecord(evQK, 0);

    // s1: V projection + vmean + base rows + broadcast, all concurrent with
    // the origin score chain and attn_flash
    cudaStreamWaitEvent(s1, evQK, 0);
    gemm_tc<1><<<dim3(DMODEL/128, MROWS/128), 256, NSTAGE*3*TILEB, s1>>>(nullptr, bkv, nullptr);
    cudaEventRecord(evV, s1);
    vmean_part<<<dim3(KSPLIT, BATCH*NHEAD), 64, 0, s1>>>();
    vmean_fin<<<BATCH*NHEAD, 64, 0, s1>>>();
    base_out_kernel<<<BATCH*DMODEL/8, 256, 0, s1>>>(Wout, bout);
    broadcast_base<<<MROWS*DMODEL/1024, 256, 0, s1>>>(out);
    cudaEventRecord(evS1, s1);

    // origin: selection chain (needs sel_clear done on s1 before topk writes selu)
    score_m_kernel<<<BHL/16, 256>>>(idxs);
    cudaStreamWaitEvent(0, evClr, 0);
    topk_kernel<<<BATCH*NHEAD, 256>>>();
    compact_kernel<<<BATCH, 256>>>();

    // join: attention needs V + selection
    cudaStreamWaitEvent(0, evV, 0);
    attn_flash<<<dim3(KSPLIT, BATCH*NHEAD), 256, attn_smem>>>();
    attn_combine<<<BATCH*NHEAD*UTOP, 64>>>();

    // build_cmod needs vmean (s1) + ctx + rowlist; gemm2 needs broadcast (s1)
    cudaStreamWaitEvent(0, evS1, 0);
    build_cmod<<<BATCH*MODROWS*DMODEL/256, 256>>>();
    gemm_tc<2><<<dim3(8, BATCH*MODROWS/128), 256, NSTAGE*3*TILEB>>>(bout, nullptr, out);
}

// round 17
// speedup vs baseline: 1.2715x; 1.0293x over previous
#include <cuda_runtime.h>
#include <cuda_bf16.h>
#include <cuda_fp16.h>
#include <cstdint>
#include <math.h>

#define BATCH 2
#define LSEQ 2048
#define DMODEL 1024
#define NHEAD 16
#define DHEAD 64
#define UTOP 40
#define MROWS (BATCH*LSEQ)          // 4096
#define BHL (BATCH*NHEAD*LSEQ)      // 65536
#define KSPLIT 8
#define KS_KEYS (LSEQ/KSPLIT)       // 256
#define MODROWS 640
#define DD (DMODEL*DMODEL)

// ---------------- scratch ----------------
__device__ float g_Q[BATCH*NHEAD*LSEQ*DHEAD];
__device__ float g_K[BATCH*NHEAD*LSEQ*DHEAD];
__device__ float g_V[BATCH*NHEAD*LSEQ*DHEAD];
__device__ float g_M[BHL];
__device__ int   g_top[BATCH*NHEAD*UTOP];
__device__ float g_ctx[BATCH*NHEAD*UTOP*DHEAD];
__device__ float g_vpart[BATCH*NHEAD*KSPLIT*DHEAD];
__device__ float g_vmean[BATCH*NHEAD*DHEAD];
__device__ __nv_bfloat16 g_xbh[MROWS*DMODEL], g_xbl[MROWS*DMODEL];
__device__ __half        g_xfh[MROWS*DMODEL], g_xfl[MROWS*DMODEL];
__device__ __nv_bfloat16 g_wbh[2*DD], g_wbl[2*DD];   // [Wq ; Wkv_K] bf16 hi/lo
__device__ __half        g_wv[DD];                   // Wkv_V fp16
__device__ __half        g_wo[DD];                   // Wout fp16
__device__ __half        g_cmh[BATCH*MODROWS*DMODEL], g_cml[BATCH*MODROWS*DMODEL];
__device__ float g_pm[BATCH*NHEAD*UTOP*KSPLIT];
__device__ float g_ps[BATCH*NHEAD*UTOP*KSPLIT];
__device__ float g_pa[BATCH*NHEAD*UTOP*KSPLIT*DHEAD];
__device__ unsigned char g_selu[BATCH*NHEAD*LSEQ];
__device__ int   g_flags[BATCH*LSEQ];
__device__ int   g_rowlist[BATCH*MODROWS];
__device__ float g_baseout[BATCH*DMODEL];

// ================= helpers =================
#define CP_ASYNC16(dst, src) \
    asm volatile("cp.async.cg.shared.global [%0], [%1], 16;" :: "r"(dst), "l"(src))
#define CP_COMMIT() asm volatile("cp.async.commit_group;" ::: "memory")

__device__ __forceinline__ uint32_t smem_u32(const void* p) {
    uint32_t a;
    asm("{ .reg .u64 t; cvta.to.shared.u64 t, %1; cvt.u32.u64 %0, t; }" : "=r"(a) : "l"(p));
    return a;
}
__device__ __forceinline__ void mma_bf(float* c, const uint32_t* a, const uint32_t* b) {
    asm volatile("mma.sync.aligned.m16n8k16.row.col.f32.bf16.bf16.f32 "
        "{%0,%1,%2,%3}, {%4,%5,%6,%7}, {%8,%9}, {%0,%1,%2,%3};"
        : "+f"(c[0]), "+f"(c[1]), "+f"(c[2]), "+f"(c[3])
        : "r"(a[0]), "r"(a[1]), "r"(a[2]), "r"(a[3]), "r"(b[0]), "r"(b[1]));
}
__device__ __forceinline__ void mma_f16(float* c, const uint32_t* a, const uint32_t* b) {
    asm volatile("mma.sync.aligned.m16n8k16.row.col.f32.f16.f16.f32 "
        "{%0,%1,%2,%3}, {%4,%5,%6,%7}, {%8,%9}, {%0,%1,%2,%3};"
        : "+f"(c[0]), "+f"(c[1]), "+f"(c[2]), "+f"(c[3])
        : "r"(a[0]), "r"(a[1]), "r"(a[2]), "r"(a[3]), "r"(b[0]), "r"(b[1]));
}
__device__ __forceinline__ void ldsm_x4(uint32_t* r, uint32_t addr) {
    asm volatile("ldmatrix.sync.aligned.m8n8.x4.shared.b16 {%0,%1,%2,%3}, [%4];"
        : "=r"(r[0]), "=r"(r[1]), "=r"(r[2]), "=r"(r[3]) : "r"(addr));
}
// 64B rows, 4x16B blocks, XOR swizzle by row&3
__device__ __forceinline__ uint32_t sw_addr(uint32_t tile, int row, int cb) {
    return tile + (uint32_t)row * 64 + (uint32_t)((cb ^ (row & 3)) << 4);
}

// ================= conversions (float4 vectorized) =================
__global__ void splitX(const float* __restrict__ src)
{
    int i = (blockIdx.x * blockDim.x + threadIdx.x) * 4;
    float4 v = *(const float4*)(src + i);
    float a[4] = {v.x, v.y, v.z, v.w};
    __nv_bfloat16 b16[4], b16l[4];
    __half h16[4], h16l[4];
    #pragma unroll
    for (int j = 0; j < 4; j++) {
        b16[j] = __float2bfloat16(a[j]);
        b16l[j] = __float2bfloat16(a[j] - __bfloat162float(b16[j]));
        h16[j] = __float2half(a[j]);
        h16l[j] = __float2half(a[j] - __half2float(h16[j]));
    }
    __nv_bfloat162 bh0{b16[0],b16[1]}, bh1{b16[2],b16[3]}, bl0{b16l[0],b16l[1]}, bl1{b16l[2],b16l[3]};
    __half2 fh0{h16[0],h16[1]}, fh1{h16[2],h16[3]}, fl0{h16l[0],h16l[1]}, fl1{h16l[2],h16l[3]};
    *(__nv_bfloat162*)(g_xbh + i) = bh0; *(__nv_bfloat162*)(g_xbh + i + 2) = bh1;
    *(__nv_bfloat162*)(g_xbl + i) = bl0; *(__nv_bfloat162*)(g_xbl + i + 2) = bl1;
    *(__half2*)(g_xfh + i) = fh0; *(__half2*)(g_xfh + i + 2) = fh1;
    *(__half2*)(g_xfl + i) = fl0; *(__half2*)(g_xfl + i + 2) = fl1;
}
__global__ void splitWb(const float* __restrict__ Wq, const float* __restrict__ Wkv)
{
    int i = (blockIdx.x * blockDim.x + threadIdx.x) * 4;
    float4 v = (i < DD) ? *(const float4*)(Wq + i) : *(const float4*)(Wkv + i - DD);
    float a[4] = {v.x, v.y, v.z, v.w};
    __nv_bfloat16 h[4], l[4];
    #pragma unroll
    for (int j = 0; j < 4; j++) {
        h[j] = __float2bfloat16(a[j]);
        l[j] = __float2bfloat16(a[j] - __bfloat162float(h[j]));
    }
    __nv_bfloat162 h0{h[0],h[1]}, h1{h[2],h[3]}, l0{l[0],l[1]}, l1{l[2],l[3]};
    *(__nv_bfloat162*)(g_wbh + i) = h0; *(__nv_bfloat162*)(g_wbh + i + 2) = h1;
    *(__nv_bfloat162*)(g_wbl + i) = l0; *(__nv_bfloat162*)(g_wbl + i + 2) = l1;
}
__global__ void convH(const float* __restrict__ Wkv, const float* __restrict__ Wout)
{
    int i = (blockIdx.x * blockDim.x + threadIdx.x) * 4;
    float4 v = (i < DD) ? *(const float4*)(Wkv + DD + i) : *(const float4*)(Wout + i - DD);
    __half2 h0, h1;
    h0.x = __float2half(v.x); h0.y = __float2half(v.y);
    h1.x = __float2half(v.z); h1.y = __float2half(v.w);
    __half* dst = (i < DD) ? (g_wv + i) : (g_wo + i - DD);
    *(__half2*)dst = h0; *(__half2*)(dst + 2) = h1;
}

// ================= tensor-core GEMM (128x128 tile, warp 32x64) =================
#define TILEB 8192                   // 128 rows x 64B
#define NCHUNK 32
#define NSTAGE 3

template<int MODE>
__global__ void __launch_bounds__(256, 2) gemm_tc(
    const float* __restrict__ bias0, const float* __restrict__ bias1,
    float* __restrict__ out, int m_base)
{
    constexpr int NT = (MODE == 0) ? 4 : 3;
    constexpr int STAGE = NT * TILEB;
    extern __shared__ char smem[];
    uint32_t sb = smem_u32(smem);
    const int t = threadIdx.x;
    const int wid = t >> 5;
    const int lane = t & 31;
    const int g  = lane >> 2;
    const int tg = lane & 3;
    const int wm = wid >> 1;
    const int wn = wid & 1;
    const int m0 = m_base + blockIdx.y * 128;
    const int n0 = blockIdx.x * 128;

    const char *A0, *A1, *B0, *B1 = nullptr;
    if (MODE == 0) { A0 = (const char*)g_xbh; A1 = (const char*)g_xbl;
                     B0 = (const char*)g_wbh; B1 = (const char*)g_wbl; }
    else if (MODE == 1) { A0 = (const char*)g_xfh; A1 = (const char*)g_xfl;
                          B0 = (const char*)g_wv; }
    else { A0 = (const char*)g_cmh; A1 = (const char*)g_cml;
           B0 = (const char*)g_wo; }

    const int arow = lane & 15;
    const int acb  = (lane >> 4) & 1;
    const int brow = (lane & 7) + ((lane >> 4) & 1) * 8;
    const int bcb  = (lane >> 3) & 1;

    float c[2][8][4];
    #pragma unroll
    for (int i = 0; i < 2; i++)
        #pragma unroll
        for (int j = 0; j < 8; j++)
            #pragma unroll
            for (int q = 0; q < 4; q++) c[i][j][q] = 0.f;

    auto load_chunk = [&](uint32_t stage, int kc) {
        int kb = kc * 64;
        #pragma unroll
        for (int r = 0; r < 2; r++) {
            int j   = t + r * 256;
            int row = j >> 2;
            int cb  = j & 3;
            uint32_t d = (uint32_t)row * 64 + (uint32_t)((cb ^ (row & 3)) << 4);
            int off = kb + cb * 16;
            CP_ASYNC16(stage + 0*TILEB + d, A0 + (size_t)(m0 + row) * 2048 + off);
            CP_ASYNC16(stage + 1*TILEB + d, A1 + (size_t)(m0 + row) * 2048 + off);
            CP_ASYNC16(stage + 2*TILEB + d, B0 + (size_t)(n0 + row) * 2048 + off);
            if (NT == 4)
                CP_ASYNC16(stage + 3*TILEB + d, B1 + (size_t)(n0 + row) * 2048 + off);
        }
    };

    load_chunk(sb, 0);               CP_COMMIT();
    load_chunk(sb + STAGE, 1);       CP_COMMIT();

    int stg = 0;
    for (int kc = 0; kc < NCHUNK; kc++) {
        if (kc < NCHUNK - 1) asm volatile("cp.async.wait_group 1;" ::: "memory");
        else                 asm volatile("cp.async.wait_group 0;" ::: "memory");
        __syncthreads();

        uint32_t Ah = sb + stg * STAGE + 0*TILEB;
        uint32_t Al = sb + stg * STAGE + 1*TILEB;
        uint32_t Bh = sb + stg * STAGE + 2*TILEB;
        uint32_t Bl = Bh + TILEB;

        #pragma unroll
        for (int ks = 0; ks < 2; ks++) {
            uint32_t ah[2][4], al[2][4];
            #pragma unroll
            for (int i = 0; i < 2; i++) {
                int row = wm * 32 + i * 16 + arow;
                int cb  = ks * 2 + acb;
                ldsm_x4(ah[i], sw_addr(Ah, row, cb));
                ldsm_x4(al[i], sw_addr(Al, row, cb));
            }
            #pragma unroll
            for (int jj = 0; jj < 4; jj++) {
                int row = wn * 64 + jj * 16 + brow;
                int cb  = ks * 2 + bcb;
                if (MODE == 0) {
                    uint32_t bh[4], bl[4];
                    ldsm_x4(bh, sw_addr(Bh, row, cb));
                    ldsm_x4(bl, sw_addr(Bl, row, cb));
                    #pragma unroll
                    for (int i = 0; i < 2; i++) {
                        mma_bf(c[i][2*jj],   ah[i], bh);
                        mma_bf(c[i][2*jj],   ah[i], bl);
                        mma_bf(c[i][2*jj],   al[i], bh);
                        mma_bf(c[i][2*jj+1], ah[i], bh + 2);
                        mma_bf(c[i][2*jj+1], ah[i], bl + 2);
                        mma_bf(c[i][2*jj+1], al[i], bh + 2);
                    }
                } else {
                    uint32_t bq[4];
                    ldsm_x4(bq, sw_addr(Bh, row, cb));
                    #pragma unroll
                    for (int i = 0; i < 2; i++) {
                        mma_f16(c[i][2*jj],   ah[i], bq);
                        mma_f16(c[i][2*jj],   al[i], bq);
                        mma_f16(c[i][2*jj+1], ah[i], bq + 2);
                        mma_f16(c[i][2*jj+1], al[i], bq + 2);
                    }
                }
            }
        }
        if (kc + 2 < NCHUNK) {
            int nstg = stg + 2; if (nstg >= NSTAGE) nstg -= NSTAGE;
            load_chunk(sb + nstg * STAGE, kc + 2);
            CP_COMMIT();
        }
        stg = (stg + 1 == NSTAGE) ? 0 : stg + 1;
    }

    // epilogue
    #pragma unroll
    for (int i = 0; i < 2; i++) {
        #pragma unroll
        for (int j = 0; j < 8; j++) {
            #pragma unroll
            for (int half = 0; half < 2; half++) {
                int m = m0 + wm * 32 + i * 16 + g + half * 8;
                int n = n0 + wn * 64 + j * 8 + 2 * tg;
                float v0 = c[i][j][half*2 + 0];
                float v1 = c[i][j][half*2 + 1];
                if (MODE == 0) {
                    int b_ = m >> 11, l = m & (LSEQ - 1);
                    int nloc = n & 1023;
                    int h = nloc >> 6, dh = nloc & 63;
                    const float* bias = (n < DMODEL) ? (bias0 + n) : (bias1 + n - DMODEL);
                    float* dst = ((n < DMODEL) ? g_Q : g_K)
                               + (((size_t)(b_ * NHEAD + h)) * LSEQ + l) * DHEAD + dh;
                    *(float2*)dst = make_float2(v0 + bias[0], v1 + bias[1]);
                } else if (MODE == 1) {
                    int b_ = m >> 11, l = m & (LSEQ - 1);
                    int h = n >> 6, dh = n & 63;
                    const float* bias = bias1 + DMODEL + n;
                    float* dst = g_V + (((size_t)(b_ * NHEAD + h)) * LSEQ + l) * DHEAD + dh;
                    *(float2*)dst = make_float2(v0 + bias[0], v1 + bias[1]);
                } else {
                    int b_ = m / MODROWS;
                    int i_ = m - b_ * MODROWS;
                    int l  = g_rowlist[b_ * MODROWS + i_];
                    *(float2*)(out + ((size_t)(b_ * LSEQ + l)) * DMODEL + n) =
                        make_float2(v0 + bias0[n], v1 + bias0[n + 1]);
                }
            }
        }
    }
}

// ================= M scores (fp32, 2 queries per warp, bh half) ===============
__global__ void score_m_kernel(const int* __restrict__ idxs, int bh_base)
{
    int warp = (blockIdx.x * blockDim.x + threadIdx.x) >> 5;
    int lane = threadIdx.x & 31;
    int bh = bh_base + warp / (LSEQ/2);
    int l0 = (warp % (LSEQ/2)) * 2;
    const float* qr = g_Q + ((size_t)bh*LSEQ + l0) * DHEAD;
    float qa0 = qr[lane],         qa1 = qr[lane + 32];
    float qb0 = qr[DHEAD + lane], qb1 = qr[DHEAD + lane + 32];
    float mxa = -1e30f, sma = 0.f;
    float mxb = -1e30f, smb = 0.f;
    const float* Kb = g_K + (size_t)bh*LSEQ*DHEAD;
    #pragma unroll 4
    for (int u = 0; u < UTOP; u++) {
        int kia = idxs[l0*UTOP + u];
        int kib = idxs[(l0+1)*UTOP + u];
        const float* kra = Kb + (size_t)kia*DHEAD;
        const float* krb = Kb + (size_t)kib*DHEAD;
        float sa = qa0*kra[lane] + qa1*kra[lane + 32];
        float sb = qb0*krb[lane] + qb1*krb[lane + 32];
        #pragma unroll
        for (int o = 16; o; o >>= 1) {
            sa += __shfl_xor_sync(0xffffffffu, sa, o);
            sb += __shfl_xor_sync(0xffffffffu, sb, o);
        }
        mxa = fmaxf(mxa, sa); sma += sa;
        mxb = fmaxf(mxb, sb); smb += sb;
    }
    if (lane == 0) {
        g_M[(size_t)bh*LSEQ + l0]     = mxa - sma * (1.0f / UTOP);
        g_M[(size_t)bh*LSEQ + l0 + 1] = mxb - smb * (1.0f / UTOP);
    }
}

// ================= top-U (fused sel_mark, bh half) =================
__global__ void topk_kernel(int bh_base)
{
    int bh = bh_base + blockIdx.x;
    __shared__ float vals[LSEQ];
    __shared__ float wv[8];
    __shared__ int   wi[8];
    int t = threadIdx.x, lane = t & 31, wid = t >> 5;
    int b_ = bh / NHEAD;
    for (int i = t; i < LSEQ; i += 256) vals[i] = g_M[(size_t)bh*LSEQ + i];
    __syncthreads();
    for (int it = 0; it < UTOP; it++) {
        float v = -2e30f; int bi = 0;
        int base = t * 8;
        #pragma unroll
        for (int j = 0; j < 8; j++) {
            float x = vals[base + j];
            if (x > v) { v = x; bi = base + j; }
        }
        #pragma unroll
        for (int o = 16; o; o >>= 1) {
            float ov = __shfl_xor_sync(0xffffffffu, v, o);
            int   oi = __shfl_xor_sync(0xffffffffu, bi, o);
            if (ov > v) { v = ov; bi = oi; }
        }
        if (lane == 0) { wv[wid] = v; wi[wid] = bi; }
        __syncthreads();
        if (t < 32) {
            float v2 = (t < 8) ? wv[t] : -2e30f;
            int   i2 = (t < 8) ? wi[t] : 0;
            #pragma unroll
            for (int o = 4; o; o >>= 1) {
                float ov = __shfl_xor_sync(0xffffffffu, v2, o);
                int   oi = __shfl_xor_sync(0xffffffffu, i2, o);
                if (ov > v2) { v2 = ov; i2 = oi; }
            }
            if (t == 0) {
                g_top[bh*UTOP + it] = i2;
                g_selu[bh*LSEQ + i2] = (unsigned char)(it + 1);
                g_flags[b_*LSEQ + i2] = 1;
                vals[i2] = -1e30f;
            }
        }
        __syncthreads();
    }
}

// ================= V mean (side stream) =================
__global__ void vmean_part()
{
    int p = blockIdx.x, bh = blockIdx.y, dh = threadIdx.x;
    float s = 0.f;
    const float* base = g_V + ((size_t)bh*LSEQ + p*KS_KEYS)*DHEAD + dh;
    #pragma unroll 4
    for (int j = 0; j < KS_KEYS; j++) s += base[(size_t)j*DHEAD];
    g_vpart[((size_t)bh*KSPLIT + p)*DHEAD + dh] = s;
}
__global__ void vmean_fin()
{
    int bh = blockIdx.x, dh = threadIdx.x;
    float s = 0.f;
    #pragma unroll
    for (int p = 0; p < KSPLIT; p++) s += g_vpart[((size_t)bh*KSPLIT + p)*DHEAD + dh];
    g_vmean[bh*DHEAD + dh] = s * (1.0f / LSEQ);
}

// ================= flash-split attention =================
__global__ void attn_flash()
{
    extern __shared__ float sm[];
    float* Qt   = sm;
    float* P    = sm + UTOP*DHEAD;
    float* mrow = P + UTOP*KS_KEYS;
    float* srow = mrow + UTOP;
    int ks = blockIdx.x, bh = blockIdx.y;
    int t = threadIdx.x, lane = t & 31, wid = t >> 5;

    for (int i = t; i < UTOP*DHEAD; i += 256) {
        int u = i >> 6, d = i & 63;
        Qt[i] = g_Q[((size_t)bh*LSEQ + g_top[bh*UTOP + u])*DHEAD + d];
    }
    __syncthreads();

    int k = ks * KS_KEYS + t;
    const float4* Kr = (const float4*)(g_K + ((size_t)bh*LSEQ + k)*DHEAD);
    float S[UTOP];
    #pragma unroll
    for (int u = 0; u < UTOP; u++) S[u] = 0.f;
    #pragma unroll
    for (int c = 0; c < 16; c++) {
        float4 kv = Kr[c];
        #pragma unroll
        for (int u = 0; u < UTOP; u++) {
            float4 qv = *(const float4*)(Qt + u*DHEAD + c*4);
            S[u] += kv.x*qv.x + kv.y*qv.y + kv.z*qv.z + kv.w*qv.w;
        }
    }
    #pragma unroll
    for (int u = 0; u < UTOP; u++) P[u*KS_KEYS + t] = S[u] * 0.125f;
    __syncthreads();

    for (int i = 0; i < 5; i++) {
        int u = wid + i*8;
        float* row = P + u*KS_KEYS;
        float m = -1e30f;
        #pragma unroll
        for (int j = 0; j < 8; j++) m = fmaxf(m, row[lane + 32*j]);
        #pragma unroll
        for (int o = 16; o; o >>= 1) m = fmaxf(m, __shfl_xor_sync(0xffffffffu, m, o));
        float s = 0.f;
        #pragma unroll
        for (int j = 0; j < 8; j++) {
            float e = __expf(row[lane + 32*j] - m);
            row[lane + 32*j] = e;
            s += e;
        }
        #pragma unroll
        for (int o = 16; o; o >>= 1) s += __shfl_xor_sync(0xffffffffu, s, o);
        if (lane == 0) { mrow[u] = m; srow[u] = s; }
    }
    __syncthreads();

    int d = t & 63, ug = t >> 6;
    float acc[10];
    #pragma unroll
    for (int i = 0; i < 10; i++) acc[i] = 0.f;
    const float* Vb = g_V + ((size_t)bh*LSEQ + ks*KS_KEYS)*DHEAD + d;
    for (int kc = 0; kc < KS_KEYS/4; kc++) {
        float v0 = Vb[(size_t)(kc*4+0)*DHEAD];
        float v1 = Vb[(size_t)(kc*4+1)*DHEAD];
        float v2 = Vb[(size_t)(kc*4+2)*DHEAD];
        float v3 = Vb[(size_t)(kc*4+3)*DHEAD];
        #pragma unroll
        for (int i = 0; i < 10; i++) {
            int u = ug*10 + i;
            float4 p4 = *(const float4*)(P + u*KS_KEYS + kc*4);
            acc[i] += p4.x*v0 + p4.y*v1 + p4.z*v2 + p4.w*v3;
        }
    }
    #pragma unroll
    for (int i = 0; i < 10; i++) {
        int u = ug*10 + i;
        g_pa[(((size_t)(bh*UTOP + u))*KSPLIT + ks)*DHEAD + d] = acc[i];
    }
    if (t < UTOP) {
        g_pm[(bh*UTOP + t)*KSPLIT + ks] = mrow[t];
        g_ps[(bh*UTOP + t)*KSPLIT + ks] = srow[t];
    }
}

__global__ void attn_combine()
{
    int bhu = blockIdx.x;
    int d = threadIdx.x;
    float m = -1e30f;
    #pragma unroll
    for (int j = 0; j < KSPLIT; j++) m = fmaxf(m, g_pm[bhu*KSPLIT + j]);
    float s = 0.f, a = 0.f;
    #pragma unroll
    for (int j = 0; j < KSPLIT; j++) {
        float w = __expf(g_pm[bhu*KSPLIT + j] - m);
        s += w * g_ps[bhu*KSPLIT + j];
        a += w * g_pa[((size_t)bhu*KSPLIT + j)*DHEAD + d];
    }
    g_ctx[(size_t)bhu*DHEAD + d] = a / s;
}

// ================= output-projection compaction =================
__global__ void sel_clear()      // int4-vectorized
{
    int i = blockIdx.x * blockDim.x + threadIdx.x;
    if (i < BHL/16)
        *(int4*)((int*)(void*)g_selu + i*4) = make_int4(0,0,0,0);
    else {
        int j = i - BHL/16;
        *(int4*)(g_flags + j*4) = make_int4(0,0,0,0);
    }
}
__global__ void compact_kernel()
{
    int b = blockIdx.x, t = threadIdx.x;
    __shared__ int cnts[256];
    __shared__ int l0s;
    int mine[8];
    int cnt = 0;
    #pragma unroll
    for (int j = 0; j < 8; j++) {
        mine[j] = g_flags[b*LSEQ + t*8 + j];
        cnt += mine[j];
    }
    cnts[t] = cnt;
    __syncthreads();
    for (int off = 1; off < 256; off <<= 1) {
        int v = (t >= off) ? cnts[t - off] : 0;
        __syncthreads();
        cnts[t] += v;
        __syncthreads();
    }
    int pos = cnts[t] - cnt;
    int total = cnts[255];
    #pragma unroll
    for (int j = 0; j < 8; j++)
        if (mine[j]) g_rowlist[b*MODROWS + pos++] = t*8 + j;
    __syncthreads();
    if (t == 0) l0s = g_rowlist[b*MODROWS];
    __syncthreads();
    for (int i = total + t; i < MODROWS; i += 256) g_rowlist[b*MODROWS + i] = l0s;
}
__global__ void build_cmod()
{
    int idx = blockIdx.x * blockDim.x + threadIdx.x;
    int d = idx & 1023;
    int r = (idx >> 10) % MODROWS;
    int b = idx / (MODROWS * 1024);
    int l = g_rowlist[b*MODROWS + r];
    int h = d >> 6;
    int bh = b * NHEAD + h;
    unsigned char u = g_selu[bh*LSEQ + l];
    float v = u ? g_ctx[((size_t)bh*UTOP + (u-1))*DHEAD + (d & 63)]
                : g_vmean[bh*DHEAD + (d & 63)];
    __half hi = __float2half(v);
    g_cmh[idx] = hi;
    g_cml[idx] = __float2half(v - __half2float(hi));
}
__global__ void base_out_kernel(const float* __restrict__ Wout, const float* __restrict__ bout)
{
    int gid = blockIdx.x * 8 + (threadIdx.x >> 5);
    int lane = threadIdx.x & 31;
    int b = gid >> 10, n = gid & 1023;
    const float* w = Wout + (size_t)n * DMODEL;
    const float* cb = g_vmean + b * DMODEL;
    float s = 0.f;
    #pragma unroll 8
    for (int k = lane; k < DMODEL; k += 32) s += cb[k] * w[k];
    #pragma unroll
    for (int o = 16; o; o >>= 1) s += __shfl_xor_sync(0xffffffffu, s, o);
    if (lane == 0) g_baseout[b*DMODEL + n] = s + bout[n];
}
__global__ void broadcast_base(float* __restrict__ out)
{
    int idx = blockIdx.x * blockDim.x + threadIdx.x;
    int e = idx * 4;
    int b = e >> 21;
    float4 v = *(const float4*)(g_baseout + b*DMODEL + (e & 1023));
    *(float4*)(out + e) = v;
}

// -----------------------------------------------------------------------------
extern "C" void kernel_launch(void* const* d_in, const int* in_sizes, int n_in,
                              void* d_out, int out_size)
{
    const float* x    = (const float*)d_in[0];
    const float* Wq   = (const float*)d_in[1];
    const float* bq   = (const float*)d_in[2];
    const float* Wkv  = (const float*)d_in[3];
    const float* bkv  = (const float*)d_in[4];
    const float* Wout = (const float*)d_in[5];
    const float* bout = (const float*)d_in[6];
    const int*   idxs = (const int*)d_in[7];
    float* out = (float*)d_out;

    // one-time setup: streams/events/attributes created on the FIRST call
    // (the correctness run), reused on every later call so no allocation
    // happens during or after graph capture.
    static bool initialized = false;
    static cudaStream_t s1, s2;
    static cudaEvent_t evConv, evClr, evQKh0, evQK, evV, evS1, evT0;
    if (!initialized) {
        cudaFuncSetAttribute(gemm_tc<0>, cudaFuncAttributeMaxDynamicSharedMemorySize, NSTAGE*4*TILEB);
        cudaFuncSetAttribute(gemm_tc<1>, cudaFuncAttributeMaxDynamicSharedMemorySize, NSTAGE*3*TILEB);
        cudaFuncSetAttribute(gemm_tc<2>, cudaFuncAttributeMaxDynamicSharedMemorySize, NSTAGE*3*TILEB);
        int attn_smem0 = (UTOP*DHEAD + UTOP*KS_KEYS + 2*UTOP) * sizeof(float);
        cudaFuncSetAttribute(attn_flash, cudaFuncAttributeMaxDynamicSharedMemorySize, attn_smem0);
        cudaStreamCreateWithFlags(&s1, cudaStreamNonBlocking);
        cudaStreamCreateWithFlags(&s2, cudaStreamNonBlocking);
        cudaEventCreateWithFlags(&evConv, cudaEventDisableTiming);
        cudaEventCreateWithFlags(&evClr,  cudaEventDisableTiming);
        cudaEventCreateWithFlags(&evQKh0, cudaEventDisableTiming);
        cudaEventCreateWithFlags(&evQK,   cudaEventDisableTiming);
        cudaEventCreateWithFlags(&evV,    cudaEventDisableTiming);
        cudaEventCreateWithFlags(&evS1,   cudaEventDisableTiming);
        cudaEventCreateWithFlags(&evT0,   cudaEventDisableTiming);
        initialized = true;
    }
    const int attn_smem = (UTOP*DHEAD + UTOP*KS_KEYS + 2*UTOP) * sizeof(float);

    // origin: conversions
    splitX<<<MROWS*DMODEL/1024, 256>>>(x);
    splitWb<<<2*DD/1024, 256>>>(Wq, Wkv);
    cudaEventRecord(evConv, 0);
    // s1: V/out weight conversion + selection-map clear (hidden under gemm_QK)
    cudaStreamWaitEvent(s1, evConv, 0);
    convH<<<2*DD/1024, 256, 0, s1>>>(Wkv, Wout);
    sel_clear<<<20, 256, 0, s1>>>();
    cudaEventRecord(evClr, s1);

    // origin: gemm_QK half 0 (batch 0 rows), then half 1
    gemm_tc<0><<<dim3(2*DMODEL/128, 16), 256, NSTAGE*4*TILEB>>>(bq, bkv, nullptr, 0);
    cudaEventRecord(evQKh0, 0);
    gemm_tc<0><<<dim3(2*DMODEL/128, 16), 256, NSTAGE*4*TILEB>>>(bq, bkv, nullptr, 2048);
    cudaEventRecord(evQK, 0);

    // s2: batch-0 selection, concurrent with gemm_QK half 1
    cudaStreamWaitEvent(s2, evQKh0, 0);
    cudaStreamWaitEvent(s2, evClr, 0);
    score_m_kernel<<<BHL/32, 256, 0, s2>>>(idxs, 0);
    topk_kernel<<<16, 256, 0, s2>>>(0);
    cudaEventRecord(evT0, s2);

    // s1: V projection + vmean + base rows + broadcast (hidden under selection)
    cudaStreamWaitEvent(s1, evQK, 0);
    gemm_tc<1><<<dim3(DMODEL/128, MROWS/128), 256, NSTAGE*3*TILEB, s1>>>(nullptr, bkv, nullptr, 0);
    cudaEventRecord(evV, s1);
    vmean_part<<<dim3(KSPLIT, BATCH*NHEAD), 64, 0, s1>>>();
    vmean_fin<<<BATCH*NHEAD, 64, 0, s1>>>();
    base_out_kernel<<<BATCH*DMODEL/8, 256, 0, s1>>>(Wout, bout);
    broadcast_base<<<MROWS*DMODEL/1024, 256, 0, s1>>>(out);
    cudaEventRecord(evS1, s1);

    // origin: batch-1 selection
    score_m_kernel<<<BHL/32, 256>>>(idxs, 16);
    cudaStreamWaitEvent(0, evClr, 0);
    topk_kernel<<<16, 256>>>(16);
    cudaStreamWaitEvent(0, evT0, 0);
    compact_kernel<<<BATCH, 256>>>();

    // join: attention needs V + full selection
    cudaStreamWaitEvent(0, evV, 0);
    attn_flash<<<dim3(KSPLIT, BATCH*NHEAD), 256, attn_smem>>>();
    attn_combine<<<BATCH*NHEAD*UTOP, 64>>>();

    // build_cmod needs vmean (s1) + ctx + rowlist; gemm2 needs broadcast (s1)
    cudaStreamWaitEvent(0, evS1, 0);
    build_cmod<<<BATCH*MODROWS*DMODEL/256, 256>>>();
    gemm_tc<2><<<dim3(8, BATCH*MODROWS/128), 256, NSTAGE*3*TILEB>>>(bout, nullptr, out, 0);
}